// round 8
// baseline (speedup 1.0000x reference)
#include <cuda_runtime.h>
#include <cuda_bf16.h>
#include <math.h>
#include <stdint.h>

#define BATCH 4
#define CH 64
#define NPIX 4096
#define NTOT (BATCH*CH*NPIX)

__device__ float g_y[NTOT];                // conv out -> normalized feat (B,C,N)
__device__ unsigned g_fh[BATCH*NPIX*32];   // hi bf16x2 (B,N,32)
__device__ unsigned g_fl[BATCH*NPIX*32];   // lo bf16x2
__device__ float g_stats[2*CH];
__device__ float g_po[2*BATCH*64*4096];    // partial O  [z][b][it][c][r]
__device__ float g_pm[2*BATCH*64*64];      // partial m  [z][b][it][r]
__device__ float g_pl[2*BATCH*64*64];      // partial l

__device__ __forceinline__ uint32_t smem_u32(const void* p) {
    uint32_t a;
    asm("{ .reg .u64 t; cvta.to.shared.u64 t, %1; cvt.u32.u64 %0, t; }" : "=r"(a) : "l"(p));
    return a;
}
__device__ __forceinline__ void ldsm4(uint32_t* r, uint32_t a) {
    asm volatile("ldmatrix.sync.aligned.m8n8.x4.shared.b16 {%0,%1,%2,%3}, [%4];"
        : "=r"(r[0]), "=r"(r[1]), "=r"(r[2]), "=r"(r[3]) : "r"(a));
}
__device__ __forceinline__ void ldsm4t(uint32_t* r, uint32_t a) {
    asm volatile("ldmatrix.sync.aligned.m8n8.x4.trans.shared.b16 {%0,%1,%2,%3}, [%4];"
        : "=r"(r[0]), "=r"(r[1]), "=r"(r[2]), "=r"(r[3]) : "r"(a));
}
__device__ __forceinline__ void mma(float* d, const uint32_t* a, uint32_t b0, uint32_t b1) {
    asm volatile("mma.sync.aligned.m16n8k16.row.col.f32.bf16.bf16.f32 "
        "{%0,%1,%2,%3}, {%4,%5,%6,%7}, {%8,%9}, {%0,%1,%2,%3};"
        : "+f"(d[0]), "+f"(d[1]), "+f"(d[2]), "+f"(d[3])
        : "r"(a[0]), "r"(a[1]), "r"(a[2]), "r"(a[3]), "r"(b0), "r"(b1));
}
__device__ __forceinline__ uint32_t pack_bf2(float lo, float hi) {
    uint32_t d;
    asm("cvt.rn.bf16x2.f32 %0, %1, %2;" : "=r"(d) : "f"(hi), "f"(lo));
    return d;
}

__global__ void k_init_stats() { int t = threadIdx.x; if (t < 2*CH) g_stats[t] = 0.0f; }

// -------- conv 3x3 + bias, 2 c_out per CTA (grid 128 = one wave) ----------
__global__ void __launch_bounds__(256) k_conv(const float* __restrict__ x,
                                              const float* __restrict__ w,
                                              const float* __restrict__ bvec) {
    __shared__ float xs[66*66];
    const int co0 = blockIdx.x*2, b = blockIdx.y, tid = threadIdx.x;
    for (int i = tid; i < 66*66; i += 256) xs[i] = 0.0f;
    float accA[4][4], accB[4][4];
#pragma unroll
    for (int s = 0; s < 4; s++)
#pragma unroll
        for (int e = 0; e < 4; e++) { accA[s][e]=0.f; accB[s][e]=0.f; }
    const float4* xb4 = reinterpret_cast<const float4*>(x + (size_t)b*CH*NPIX);
    for (int ci = 0; ci < CH; ci++) {
        __syncthreads();
#pragma unroll
        for (int k = 0; k < 4; k++) {
            int lin = tid + k*256;
            float4 v = xb4[ci*1024 + lin];
            float* dst = xs + ((lin>>4)+1)*66 + ((lin&15)<<2) + 1;
            dst[0]=v.x; dst[1]=v.y; dst[2]=v.z; dst[3]=v.w;
        }
        __syncthreads();
        const float* wA = w + (co0*CH + ci)*9;
        const float* wB = w + ((co0+1)*CH + ci)*9;
        float a0=wA[0],a1=wA[1],a2=wA[2],a3=wA[3],a4=wA[4],a5=wA[5],a6=wA[6],a7=wA[7],a8=wA[8];
        float b0=wB[0],b1=wB[1],b2=wB[2],b3=wB[3],b4=wB[4],b5=wB[5],b6=wB[6],b7=wB[7],b8=wB[8];
#pragma unroll
        for (int s = 0; s < 4; s++) {
            int pb = s*1024 + tid*4;
            const float* r0 = xs + (pb>>6)*66 + (pb&63);
            const float* r1 = r0 + 66; const float* r2 = r1 + 66;
            float t0,t1,t2,t3,t4,t5;
            t0=r0[0];t1=r0[1];t2=r0[2];t3=r0[3];t4=r0[4];t5=r0[5];
            accA[s][0]+=t0*a0+t1*a1+t2*a2; accA[s][1]+=t1*a0+t2*a1+t3*a2;
            accA[s][2]+=t2*a0+t3*a1+t4*a2; accA[s][3]+=t3*a0+t4*a1+t5*a2;
            accB[s][0]+=t0*b0+t1*b1+t2*b2; accB[s][1]+=t1*b0+t2*b1+t3*b2;
            accB[s][2]+=t2*b0+t3*b1+t4*b2; accB[s][3]+=t3*b0+t4*b1+t5*b2;
            t0=r1[0];t1=r1[1];t2=r1[2];t3=r1[3];t4=r1[4];t5=r1[5];
            accA[s][0]+=t0*a3+t1*a4+t2*a5; accA[s][1]+=t1*a3+t2*a4+t3*a5;
            accA[s][2]+=t2*a3+t3*a4+t4*a5; accA[s][3]+=t3*a3+t4*a4+t5*a5;
            accB[s][0]+=t0*b3+t1*b4+t2*b5; accB[s][1]+=t1*b3+t2*b4+t3*b5;
            accB[s][2]+=t2*b3+t3*b4+t4*b5; accB[s][3]+=t3*b3+t4*b4+t5*b5;
            t0=r2[0];t1=r2[1];t2=r2[2];t3=r2[3];t4=r2[4];t5=r2[5];
            accA[s][0]+=t0*a6+t1*a7+t2*a8; accA[s][1]+=t1*a6+t2*a7+t3*a8;
            accA[s][2]+=t2*a6+t3*a7+t4*a8; accA[s][3]+=t3*a6+t4*a7+t5*a8;
            accB[s][0]+=t0*b6+t1*b7+t2*b8; accB[s][1]+=t1*b6+t2*b7+t3*b8;
            accB[s][2]+=t2*b6+t3*b7+t4*b8; accB[s][3]+=t3*b6+t4*b7+t5*b8;
        }
    }
    float s1a=0.f, s2a=0.f, s1b=0.f, s2b=0.f;
    {
        const float cba = bvec[co0], cbb = bvec[co0+1];
        float4* ypA = reinterpret_cast<float4*>(g_y + (size_t)(b*CH + co0)*NPIX);
        float4* ypB = reinterpret_cast<float4*>(g_y + (size_t)(b*CH + co0 + 1)*NPIX);
#pragma unroll
        for (int s = 0; s < 4; s++) {
            float v0=accA[s][0]+cba, v1=accA[s][1]+cba, v2=accA[s][2]+cba, v3=accA[s][3]+cba;
            ypA[s*256 + tid] = make_float4(v0,v1,v2,v3);
            s1a += v0+v1+v2+v3; s2a += v0*v0+v1*v1+v2*v2+v3*v3;
            float u0=accB[s][0]+cbb, u1=accB[s][1]+cbb, u2=accB[s][2]+cbb, u3=accB[s][3]+cbb;
            ypB[s*256 + tid] = make_float4(u0,u1,u2,u3);
            s1b += u0+u1+u2+u3; s2b += u0*u0+u1*u1+u2*u2+u3*u3;
        }
    }
#pragma unroll
    for (int m = 16; m >= 1; m >>= 1) {
        s1a += __shfl_xor_sync(0xffffffffu, s1a, m);
        s2a += __shfl_xor_sync(0xffffffffu, s2a, m);
        s1b += __shfl_xor_sync(0xffffffffu, s1b, m);
        s2b += __shfl_xor_sync(0xffffffffu, s2b, m);
    }
    __syncthreads();
    if ((tid & 31) == 0) {
        int ww = tid>>5;
        xs[ww] = s1a; xs[8+ww] = s2a; xs[16+ww] = s1b; xs[24+ww] = s2b;
    }
    __syncthreads();
    if (tid == 0) {
        float r1a=0.f, r2a=0.f, r1b=0.f, r2b=0.f;
        for (int i = 0; i < 8; i++) { r1a+=xs[i]; r2a+=xs[8+i]; r1b+=xs[16+i]; r2b+=xs[24+i]; }
        atomicAdd(&g_stats[co0], r1a);      atomicAdd(&g_stats[CH+co0], r2a);
        atomicAdd(&g_stats[co0+1], r1b);    atomicAdd(&g_stats[CH+co0+1], r2b);
    }
}

// ------------- BN + PReLU; feat in-place; transposed split-bf16 out ---------
__global__ void __launch_bounds__(256) k_bnt(const float* __restrict__ scale,
                                             const float* __restrict__ bias,
                                             const float* __restrict__ pa) {
    __shared__ float t[64][65];
    __shared__ float msc[64], mof[64];
    const int b = blockIdx.y, i0 = blockIdx.x*64, tid = threadIdx.x;
    const float a = pa[0];
    if (tid < 64) {
        const float inv = 1.0f / (float)(BATCH*NPIX);
        float m = g_stats[tid]*inv, v = g_stats[CH+tid]*inv - m*m;
        float r = rsqrtf(v + 1e-5f);
        msc[tid] = r*scale[tid]; mof[tid] = bias[tid] - m*r*scale[tid];
    }
    __syncthreads();
#pragma unroll
    for (int k = 0; k < 16; k++) {
        int idx = tid + k*256, c = idx>>6, ii = idx&63;
        size_t o = (size_t)(b*CH + c)*NPIX + i0 + ii;
        float v = g_y[o]*msc[c] + mof[c];
        v = (v >= 0.f) ? v : a*v;
        g_y[o] = v; t[c][ii] = v;
    }
    __syncthreads();
#pragma unroll
    for (int k = 0; k < 8; k++) {
        int idx = tid + k*256, ii = idx>>5, cp = idx&31;
        float v0 = t[2*cp][ii], v1 = t[2*cp+1][ii];
        uint32_t u0 = __float_as_uint(v0), u1 = __float_as_uint(v1);
        uint32_t h0 = u0 & 0xffff0000u, h1 = u1 & 0xffff0000u;
        float r0 = v0 - __uint_as_float(h0), r1 = v1 - __uint_as_float(h1);
        size_t o = ((size_t)b*NPIX + i0 + ii)*32 + cp;
        g_fh[o] = h1 | (h0 >> 16);
        g_fl[o] = pack_bf2(r0, r1);
    }
}

// ----------- stage one 64x64 split tile (hi+lo, swizzled), 128 thr ---------
__device__ __forceinline__ void stg(uint32_t base, const unsigned* fh,
                                    const unsigned* fl, int j0, int tid) {
#pragma unroll
    for (int k = 0; k < 8; k++) {
        int idx = tid + k*128;
        int hilo = idx >> 9;
        int rr = (idx >> 3) & 63, q = idx & 7;
        uint32_t dst = base + (uint32_t)hilo*8192u + (uint32_t)(rr*128) +
                       (uint32_t)((q*16) ^ ((rr & 7)*16));
        const unsigned* src = (hilo ? fl : fh) + (size_t)(j0 + rr)*32 + q*4;
        asm volatile("cp.async.cg.shared.global [%0], [%1], 16;" :: "r"(dst), "l"(src));
    }
    asm volatile("cp.async.commit_group;" ::: "memory");
}

// ------- flash attention partials: (it, b, z) with z = half of j-range -----
__global__ void __launch_bounds__(128, 3) k_attn(float* __restrict__ dummy) {
    __shared__ __align__(1024) char ks[32768];
    const uint32_t ksb = smem_u32(ks);
    const int tid = threadIdx.x, w = tid >> 5, lane = tid & 31;
    const int g = lane >> 2, lam = lane & 3;
    const int it = blockIdx.x, b = blockIdx.y, z = blockIdx.z;
    const int i0 = it * 64;
    const int row0 = i0 + w*16 + g, row1 = row0 + 8;
    const int jbase = z * 32;            // 32 j-tiles per split

    const unsigned* fh = g_fh + (size_t)b*NPIX*32;
    const unsigned* fl = g_fl + (size_t)b*NPIX*32;

    uint32_t qh[4][4], ql[4][4];
#pragma unroll
    for (int kc = 0; kc < 4; kc++) {
        qh[kc][0] = fh[(size_t)row0*32 + lam + 8*kc];
        qh[kc][1] = fh[(size_t)row1*32 + lam + 8*kc];
        qh[kc][2] = fh[(size_t)row0*32 + lam + 4 + 8*kc];
        qh[kc][3] = fh[(size_t)row1*32 + lam + 4 + 8*kc];
        ql[kc][0] = fl[(size_t)row0*32 + lam + 8*kc];
        ql[kc][1] = fl[(size_t)row1*32 + lam + 8*kc];
        ql[kc][2] = fl[(size_t)row0*32 + lam + 4 + 8*kc];
        ql[kc][3] = fl[(size_t)row1*32 + lam + 4 + 8*kc];
    }

    float o[8][4];
#pragma unroll
    for (int n = 0; n < 8; n++) { o[n][0]=o[n][1]=o[n][2]=o[n][3]=0.f; }
    float m0 = -1e30f, m1 = -1e30f, l0 = 0.f, l1 = 0.f;

    stg(ksb, fh, fl, (jbase + 0)*64, tid);

    for (int jt = 0; jt < 32; jt++) {
        if (jt < 31) {
            stg(ksb + (uint32_t)(((jt+1)&1)*16384), fh, fl, (jbase + jt + 1)*64, tid);
            asm volatile("cp.async.wait_group 1;" ::: "memory");
        } else {
            asm volatile("cp.async.wait_group 0;" ::: "memory");
        }
        __syncthreads();
        const uint32_t kb = ksb + (uint32_t)((jt&1)*16384);

        // ---- S = Q.K^T (hh + hl + lh)
        float s[8][4];
#pragma unroll
        for (int n = 0; n < 8; n++) { s[n][0]=s[n][1]=s[n][2]=s[n][3]=0.f; }
#pragma unroll
        for (int jn2 = 0; jn2 < 4; jn2++) {
            const int jadr = 16*jn2 + (lane & 7) + ((lane >> 4) & 1)*8;
#pragma unroll
            for (int kc = 0; kc < 4; kc++) {
                const int q = 2*kc + ((lane >> 3) & 1);
                uint32_t ah = kb + (uint32_t)(jadr*128) + (uint32_t)((q*16) ^ ((jadr & 7)*16));
                uint32_t bh[4], bl[4];
                ldsm4(bh, ah);
                ldsm4(bl, ah + 8192u);
                mma(s[2*jn2],   qh[kc], bh[0], bh[1]);
                mma(s[2*jn2],   qh[kc], bl[0], bl[1]);
                mma(s[2*jn2],   ql[kc], bh[0], bh[1]);
                mma(s[2*jn2+1], qh[kc], bh[2], bh[3]);
                mma(s[2*jn2+1], qh[kc], bl[2], bl[3]);
                mma(s[2*jn2+1], ql[kc], bh[2], bh[3]);
            }
        }

        // ---- online softmax, score = -s
        float mt0 = -1e30f, mt1 = -1e30f;
#pragma unroll
        for (int n = 0; n < 8; n++) {
            mt0 = fmaxf(mt0, fmaxf(-s[n][0], -s[n][1]));
            mt1 = fmaxf(mt1, fmaxf(-s[n][2], -s[n][3]));
        }
        mt0 = fmaxf(mt0, __shfl_xor_sync(0xffffffffu, mt0, 1));
        mt0 = fmaxf(mt0, __shfl_xor_sync(0xffffffffu, mt0, 2));
        mt1 = fmaxf(mt1, __shfl_xor_sync(0xffffffffu, mt1, 1));
        mt1 = fmaxf(mt1, __shfl_xor_sync(0xffffffffu, mt1, 2));
        const float mn0 = fmaxf(m0, mt0), mn1 = fmaxf(m1, mt1);
        const float a0 = __expf(m0 - mn0), a1 = __expf(m1 - mn1);
        m0 = mn0; m1 = mn1;
        uint32_t ph[8][2], pl[8][2];
        float sum0 = 0.f, sum1 = 0.f;
#pragma unroll
        for (int n = 0; n < 8; n++) {
            float p00 = __expf(-s[n][0] - mn0), p01 = __expf(-s[n][1] - mn0);
            float p10 = __expf(-s[n][2] - mn1), p11 = __expf(-s[n][3] - mn1);
            sum0 += p00 + p01; sum1 += p10 + p11;
            o[n][0] *= a0; o[n][1] *= a0; o[n][2] *= a1; o[n][3] *= a1;
            uint32_t u00 = __float_as_uint(p00) & 0xffff0000u;
            uint32_t u01 = __float_as_uint(p01) & 0xffff0000u;
            uint32_t u10 = __float_as_uint(p10) & 0xffff0000u;
            uint32_t u11 = __float_as_uint(p11) & 0xffff0000u;
            ph[n][0] = u01 | (u00 >> 16);
            ph[n][1] = u11 | (u10 >> 16);
            pl[n][0] = pack_bf2(p00 - __uint_as_float(u00), p01 - __uint_as_float(u01));
            pl[n][1] = pack_bf2(p10 - __uint_as_float(u10), p11 - __uint_as_float(u11));
        }
        l0 = l0*a0 + sum0; l1 = l1*a1 + sum1;

        // ---- O += P.V (PhVh + PlVh + PhVl)
#pragma unroll
        for (int cn = 0; cn < 8; cn++) {
#pragma unroll
            for (int kjp = 0; kjp < 2; kjp++) {
                const int jadr = 32*kjp + lane;
                uint32_t ad = kb + (uint32_t)(jadr*128) + (uint32_t)((cn*16) ^ ((jadr & 7)*16));
                uint32_t vh[4], vl[4];
                ldsm4t(vh, ad);
                ldsm4t(vl, ad + 8192u);
#pragma unroll
                for (int t = 0; t < 2; t++) {
                    const int kc = 2*kjp + t;
                    uint32_t aH[4] = { ph[2*kc][0], ph[2*kc][1], ph[2*kc+1][0], ph[2*kc+1][1] };
                    uint32_t aL[4] = { pl[2*kc][0], pl[2*kc][1], pl[2*kc+1][0], pl[2*kc+1][1] };
                    mma(o[cn], aH, vh[2*t], vh[2*t+1]);
                    mma(o[cn], aL, vh[2*t], vh[2*t+1]);
                    mma(o[cn], aH, vl[2*t], vl[2*t+1]);
                }
            }
        }
        __syncthreads();
    }

    // ---- epilogue: write unnormalized partials
    l0 += __shfl_xor_sync(0xffffffffu, l0, 1);
    l0 += __shfl_xor_sync(0xffffffffu, l0, 2);
    l1 += __shfl_xor_sync(0xffffffffu, l1, 1);
    l1 += __shfl_xor_sync(0xffffffffu, l1, 2);
    const int wr0 = w*16 + g, wr1 = wr0 + 8;       // local rows
    const size_t pb = (((size_t)z*BATCH + b)*64 + it)*4096;
    const size_t mb = (((size_t)z*BATCH + b)*64 + it)*64;
    if (lam == 0) {
        g_pm[mb + wr0] = m0; g_pl[mb + wr0] = l0;
        g_pm[mb + wr1] = m1; g_pl[mb + wr1] = l1;
    }
#pragma unroll
    for (int cn = 0; cn < 8; cn++) {
        const int c0 = 8*cn + 2*lam;
        g_po[pb + (size_t)c0*64 + wr0]       = o[cn][0];
        g_po[pb + (size_t)(c0 + 1)*64 + wr0] = o[cn][1];
        g_po[pb + (size_t)c0*64 + wr1]       = o[cn][2];
        g_po[pb + (size_t)(c0 + 1)*64 + wr1] = o[cn][3];
    }
}

// ---------- combine partials: out = gamma*(sum Oz*sz)/(sum lz*sz) + feat ----
__global__ void __launch_bounds__(256) k_comb(const float* __restrict__ gp,
                                              float* __restrict__ out) {
    __shared__ float f0[64], f1[64];
    const int it = blockIdx.x, b = blockIdx.y, tid = threadIdx.x;
    if (tid < 64) {
        const size_t mb0 = (((size_t)0*BATCH + b)*64 + it)*64 + tid;
        const size_t mb1 = (((size_t)1*BATCH + b)*64 + it)*64 + tid;
        float m0 = g_pm[mb0], m1 = g_pm[mb1];
        float mm = fmaxf(m0, m1);
        float s0 = __expf(m0 - mm), s1 = __expf(m1 - mm);
        float ginv = gp[0] / (g_pl[mb0]*s0 + g_pl[mb1]*s1);
        f0[tid] = s0*ginv; f1[tid] = s1*ginv;
    }
    __syncthreads();
    const size_t p0 = (((size_t)0*BATCH + b)*64 + it)*4096;
    const size_t p1 = (((size_t)1*BATCH + b)*64 + it)*4096;
#pragma unroll
    for (int k = 0; k < 16; k++) {
        int idx = tid + k*256, c = idx >> 6, r = idx & 63;
        size_t oo = (size_t)(b*CH + c)*NPIX + it*64 + r;
        out[oo] = g_po[p0 + idx]*f0[r] + g_po[p1 + idx]*f1[r] + g_y[oo];
    }
}

extern "C" void kernel_launch(void* const* d_in, const int* in_sizes, int n_in,
                              void* d_out, int out_size) {
    const float* x     = (const float*)d_in[0];
    const float* cw    = (const float*)d_in[1];
    const float* cb    = (const float*)d_in[2];
    const float* bns   = (const float*)d_in[3];
    const float* bnb   = (const float*)d_in[4];
    const float* pa    = (const float*)d_in[5];
    const float* gamma = (const float*)d_in[6];
    float* out = (float*)d_out;

    static bool done = false;
    if (!done) {
        cudaFuncSetAttribute(k_attn, cudaFuncAttributePreferredSharedMemoryCarveout, 100);
        done = true;
    }

    k_init_stats<<<1, 128>>>();
    k_conv<<<dim3(32, BATCH), 256>>>(x, cw, cb);
    k_bnt<<<dim3(64, BATCH), 256>>>(bns, bnb, pa);
    k_attn<<<dim3(64, BATCH, 2), 128>>>(out);
    k_comb<<<dim3(64, BATCH), 256>>>(gamma, out);
}

// round 9
// speedup vs baseline: 1.0479x; 1.0479x over previous
#include <cuda_runtime.h>
#include <cuda_bf16.h>
#include <math.h>
#include <stdint.h>

#define BATCH 4
#define CH 64
#define NPIX 4096
#define NTOT (BATCH*CH*NPIX)

__device__ float g_y[NTOT];                // conv out -> normalized feat (B,C,N)
__device__ unsigned g_fh[BATCH*NPIX*32];   // hi bf16x2 (B,N,32)
__device__ unsigned g_fl[BATCH*NPIX*32];   // lo bf16x2
__device__ float g_stats[2*CH];

__device__ __forceinline__ uint32_t smem_u32(const void* p) {
    uint32_t a;
    asm("{ .reg .u64 t; cvta.to.shared.u64 t, %1; cvt.u32.u64 %0, t; }" : "=r"(a) : "l"(p));
    return a;
}
__device__ __forceinline__ void ldsm4(uint32_t* r, uint32_t a) {
    asm volatile("ldmatrix.sync.aligned.m8n8.x4.shared.b16 {%0,%1,%2,%3}, [%4];"
        : "=r"(r[0]), "=r"(r[1]), "=r"(r[2]), "=r"(r[3]) : "r"(a));
}
__device__ __forceinline__ void ldsm4t(uint32_t* r, uint32_t a) {
    asm volatile("ldmatrix.sync.aligned.m8n8.x4.trans.shared.b16 {%0,%1,%2,%3}, [%4];"
        : "=r"(r[0]), "=r"(r[1]), "=r"(r[2]), "=r"(r[3]) : "r"(a));
}
__device__ __forceinline__ void mma(float* d, const uint32_t* a, uint32_t b0, uint32_t b1) {
    asm volatile("mma.sync.aligned.m16n8k16.row.col.f32.bf16.bf16.f32 "
        "{%0,%1,%2,%3}, {%4,%5,%6,%7}, {%8,%9}, {%0,%1,%2,%3};"
        : "+f"(d[0]), "+f"(d[1]), "+f"(d[2]), "+f"(d[3])
        : "r"(a[0]), "r"(a[1]), "r"(a[2]), "r"(a[3]), "r"(b0), "r"(b1));
}
__device__ __forceinline__ uint32_t pack_bf2(float lo, float hi) {
    uint32_t d;
    asm("cvt.rn.bf16x2.f32 %0, %1, %2;" : "=r"(d) : "f"(hi), "f"(lo));
    return d;
}

__global__ void k_init_stats() { int t = threadIdx.x; if (t < 2*CH) g_stats[t] = 0.0f; }

// -------- conv 3x3 + bias, 2 c_out per CTA (grid 128 = one wave) ----------
__global__ void __launch_bounds__(256) k_conv(const float* __restrict__ x,
                                              const float* __restrict__ w,
                                              const float* __restrict__ bvec) {
    __shared__ float xs[66*66];
    const int co0 = blockIdx.x*2, b = blockIdx.y, tid = threadIdx.x;
    for (int i = tid; i < 66*66; i += 256) xs[i] = 0.0f;
    float accA[4][4], accB[4][4];
#pragma unroll
    for (int s = 0; s < 4; s++)
#pragma unroll
        for (int e = 0; e < 4; e++) { accA[s][e]=0.f; accB[s][e]=0.f; }
    const float4* xb4 = reinterpret_cast<const float4*>(x + (size_t)b*CH*NPIX);
    for (int ci = 0; ci < CH; ci++) {
        __syncthreads();
#pragma unroll
        for (int k = 0; k < 4; k++) {
            int lin = tid + k*256;
            float4 v = xb4[ci*1024 + lin];
            float* dst = xs + ((lin>>4)+1)*66 + ((lin&15)<<2) + 1;
            dst[0]=v.x; dst[1]=v.y; dst[2]=v.z; dst[3]=v.w;
        }
        __syncthreads();
        const float* wA = w + (co0*CH + ci)*9;
        const float* wB = w + ((co0+1)*CH + ci)*9;
        float a0=wA[0],a1=wA[1],a2=wA[2],a3=wA[3],a4=wA[4],a5=wA[5],a6=wA[6],a7=wA[7],a8=wA[8];
        float b0=wB[0],b1=wB[1],b2=wB[2],b3=wB[3],b4=wB[4],b5=wB[5],b6=wB[6],b7=wB[7],b8=wB[8];
#pragma unroll
        for (int s = 0; s < 4; s++) {
            int pb = s*1024 + tid*4;
            const float* r0 = xs + (pb>>6)*66 + (pb&63);
            const float* r1 = r0 + 66; const float* r2 = r1 + 66;
            float t0,t1,t2,t3,t4,t5;
            t0=r0[0];t1=r0[1];t2=r0[2];t3=r0[3];t4=r0[4];t5=r0[5];
            accA[s][0]+=t0*a0+t1*a1+t2*a2; accA[s][1]+=t1*a0+t2*a1+t3*a2;
            accA[s][2]+=t2*a0+t3*a1+t4*a2; accA[s][3]+=t3*a0+t4*a1+t5*a2;
            accB[s][0]+=t0*b0+t1*b1+t2*b2; accB[s][1]+=t1*b0+t2*b1+t3*b2;
            accB[s][2]+=t2*b0+t3*b1+t4*b2; accB[s][3]+=t3*b0+t4*b1+t5*b2;
            t0=r1[0];t1=r1[1];t2=r1[2];t3=r1[3];t4=r1[4];t5=r1[5];
            accA[s][0]+=t0*a3+t1*a4+t2*a5; accA[s][1]+=t1*a3+t2*a4+t3*a5;
            accA[s][2]+=t2*a3+t3*a4+t4*a5; accA[s][3]+=t3*a3+t4*a4+t5*a5;
            accB[s][0]+=t0*b3+t1*b4+t2*b5; accB[s][1]+=t1*b3+t2*b4+t3*b5;
            accB[s][2]+=t2*b3+t3*b4+t4*b5; accB[s][3]+=t3*b3+t4*b4+t5*b5;
            t0=r2[0];t1=r2[1];t2=r2[2];t3=r2[3];t4=r2[4];t5=r2[5];
            accA[s][0]+=t0*a6+t1*a7+t2*a8; accA[s][1]+=t1*a6+t2*a7+t3*a8;
            accA[s][2]+=t2*a6+t3*a7+t4*a8; accA[s][3]+=t3*a6+t4*a7+t5*a8;
            accB[s][0]+=t0*b6+t1*b7+t2*b8; accB[s][1]+=t1*b6+t2*b7+t3*b8;
            accB[s][2]+=t2*b6+t3*b7+t4*b8; accB[s][3]+=t3*b6+t4*b7+t5*b8;
        }
    }
    float s1a=0.f, s2a=0.f, s1b=0.f, s2b=0.f;
    {
        const float cba = bvec[co0], cbb = bvec[co0+1];
        float4* ypA = reinterpret_cast<float4*>(g_y + (size_t)(b*CH + co0)*NPIX);
        float4* ypB = reinterpret_cast<float4*>(g_y + (size_t)(b*CH + co0 + 1)*NPIX);
#pragma unroll
        for (int s = 0; s < 4; s++) {
            float v0=accA[s][0]+cba, v1=accA[s][1]+cba, v2=accA[s][2]+cba, v3=accA[s][3]+cba;
            ypA[s*256 + tid] = make_float4(v0,v1,v2,v3);
            s1a += v0+v1+v2+v3; s2a += v0*v0+v1*v1+v2*v2+v3*v3;
            float u0=accB[s][0]+cbb, u1=accB[s][1]+cbb, u2=accB[s][2]+cbb, u3=accB[s][3]+cbb;
            ypB[s*256 + tid] = make_float4(u0,u1,u2,u3);
            s1b += u0+u1+u2+u3; s2b += u0*u0+u1*u1+u2*u2+u3*u3;
        }
    }
#pragma unroll
    for (int m = 16; m >= 1; m >>= 1) {
        s1a += __shfl_xor_sync(0xffffffffu, s1a, m);
        s2a += __shfl_xor_sync(0xffffffffu, s2a, m);
        s1b += __shfl_xor_sync(0xffffffffu, s1b, m);
        s2b += __shfl_xor_sync(0xffffffffu, s2b, m);
    }
    __syncthreads();
    if ((tid & 31) == 0) {
        int ww = tid>>5;
        xs[ww] = s1a; xs[8+ww] = s2a; xs[16+ww] = s1b; xs[24+ww] = s2b;
    }
    __syncthreads();
    if (tid == 0) {
        float r1a=0.f, r2a=0.f, r1b=0.f, r2b=0.f;
        for (int i = 0; i < 8; i++) { r1a+=xs[i]; r2a+=xs[8+i]; r1b+=xs[16+i]; r2b+=xs[24+i]; }
        atomicAdd(&g_stats[co0], r1a);      atomicAdd(&g_stats[CH+co0], r2a);
        atomicAdd(&g_stats[co0+1], r1b);    atomicAdd(&g_stats[CH+co0+1], r2b);
    }
}

// ------------- BN + PReLU; feat in-place; transposed split-bf16 out ---------
__global__ void __launch_bounds__(256) k_bnt(const float* __restrict__ scale,
                                             const float* __restrict__ bias,
                                             const float* __restrict__ pa) {
    __shared__ float t[64][65];
    __shared__ float msc[64], mof[64];
    const int b = blockIdx.y, i0 = blockIdx.x*64, tid = threadIdx.x;
    const float a = pa[0];
    if (tid < 64) {
        const float inv = 1.0f / (float)(BATCH*NPIX);
        float m = g_stats[tid]*inv, v = g_stats[CH+tid]*inv - m*m;
        float r = rsqrtf(v + 1e-5f);
        msc[tid] = r*scale[tid]; mof[tid] = bias[tid] - m*r*scale[tid];
    }
    __syncthreads();
#pragma unroll
    for (int k = 0; k < 16; k++) {
        int idx = tid + k*256, c = idx>>6, ii = idx&63;
        size_t o = (size_t)(b*CH + c)*NPIX + i0 + ii;
        float v = g_y[o]*msc[c] + mof[c];
        v = (v >= 0.f) ? v : a*v;
        g_y[o] = v; t[c][ii] = v;
    }
    __syncthreads();
#pragma unroll
    for (int k = 0; k < 8; k++) {
        int idx = tid + k*256, ii = idx>>5, cp = idx&31;
        float v0 = t[2*cp][ii], v1 = t[2*cp+1][ii];
        uint32_t u0 = __float_as_uint(v0), u1 = __float_as_uint(v1);
        uint32_t h0 = u0 & 0xffff0000u, h1 = u1 & 0xffff0000u;
        float r0 = v0 - __uint_as_float(h0), r1 = v1 - __uint_as_float(h1);
        size_t o = ((size_t)b*NPIX + i0 + ii)*32 + cp;
        g_fh[o] = h1 | (h0 >> 16);
        g_fl[o] = pack_bf2(r0, r1);
    }
}

// ----------- stage one 64x64 split tile (hi+lo, swizzled), 256 thr ---------
__device__ __forceinline__ void stg(uint32_t base, const unsigned* fh,
                                    const unsigned* fl, int j0, int tid) {
#pragma unroll
    for (int k = 0; k < 4; k++) {
        int idx = tid + k*256;
        int hilo = idx >> 9;
        int rr = (idx >> 3) & 63, q = idx & 7;
        uint32_t dst = base + (uint32_t)hilo*8192u + (uint32_t)(rr*128) +
                       (uint32_t)((q*16) ^ ((rr & 7)*16));
        const unsigned* src = (hilo ? fl : fh) + (size_t)(j0 + rr)*32 + q*4;
        asm volatile("cp.async.cg.shared.global [%0], [%1], 16;" :: "r"(dst), "l"(src));
    }
    asm volatile("cp.async.commit_group;" ::: "memory");
}

// ---- flash attention: 64-row tile, 256 thr, warp = (rowgroup, jhalf) ------
__global__ void __launch_bounds__(256, 2) k_attn(const float* __restrict__ gp,
                                                 float* __restrict__ out) {
    __shared__ __align__(1024) char ks[32768];   // 2 bufs x (hi 8K + lo 8K); reused as O-combine
    __shared__ float mex[2][64], lex[2][64];
    const uint32_t ksb = smem_u32(ks);
    const int tid = threadIdx.x, w = tid >> 5, lane = tid & 31;
    const int g = lane >> 2, lam = lane & 3;
    const int wg = w >> 1, jhalf = w & 1;
    const int it = blockIdx.x, b = blockIdx.y;
    const int i0 = it * 64;
    const int row0 = i0 + wg*16 + g, row1 = row0 + 8;

    const unsigned* fh = g_fh + (size_t)b*NPIX*32;
    const unsigned* fl = g_fl + (size_t)b*NPIX*32;

    uint32_t qh[4][4], ql[4][4];
#pragma unroll
    for (int kc = 0; kc < 4; kc++) {
        qh[kc][0] = fh[(size_t)row0*32 + lam + 8*kc];
        qh[kc][1] = fh[(size_t)row1*32 + lam + 8*kc];
        qh[kc][2] = fh[(size_t)row0*32 + lam + 4 + 8*kc];
        qh[kc][3] = fh[(size_t)row1*32 + lam + 4 + 8*kc];
        ql[kc][0] = fl[(size_t)row0*32 + lam + 8*kc];
        ql[kc][1] = fl[(size_t)row1*32 + lam + 8*kc];
        ql[kc][2] = fl[(size_t)row0*32 + lam + 4 + 8*kc];
        ql[kc][3] = fl[(size_t)row1*32 + lam + 4 + 8*kc];
    }

    float o[8][4];
#pragma unroll
    for (int n = 0; n < 8; n++) { o[n][0]=o[n][1]=o[n][2]=o[n][3]=0.f; }
    float m0 = -1e30f, m1 = -1e30f, l0 = 0.f, l1 = 0.f;

    stg(ksb, fh, fl, 0, tid);

    for (int jt = 0; jt < 64; jt++) {
        if (jt < 63) {
            stg(ksb + (uint32_t)(((jt+1)&1)*16384), fh, fl, (jt+1)*64, tid);
            asm volatile("cp.async.wait_group 1;" ::: "memory");
        } else {
            asm volatile("cp.async.wait_group 0;" ::: "memory");
        }
        __syncthreads();
        const uint32_t kb = ksb + (uint32_t)((jt&1)*16384);

        // ---- S = Q.K^T over this warp's 32-col j-half (hh + hl + lh)
        float s[4][4];
#pragma unroll
        for (int n = 0; n < 4; n++) { s[n][0]=s[n][1]=s[n][2]=s[n][3]=0.f; }
#pragma unroll
        for (int jn2 = 0; jn2 < 2; jn2++) {
            const int jadr = jhalf*32 + 16*jn2 + (lane & 7) + ((lane >> 4) & 1)*8;
#pragma unroll
            for (int kc = 0; kc < 4; kc++) {
                const int q = 2*kc + ((lane >> 3) & 1);
                uint32_t ah = kb + (uint32_t)(jadr*128) + (uint32_t)((q*16) ^ ((jadr & 7)*16));
                uint32_t bh[4], bl[4];
                ldsm4(bh, ah);
                ldsm4(bl, ah + 8192u);
                mma(s[2*jn2],   qh[kc], bh[0], bh[1]);
                mma(s[2*jn2],   qh[kc], bl[0], bl[1]);
                mma(s[2*jn2],   ql[kc], bh[0], bh[1]);
                mma(s[2*jn2+1], qh[kc], bh[2], bh[3]);
                mma(s[2*jn2+1], qh[kc], bl[2], bl[3]);
                mma(s[2*jn2+1], ql[kc], bh[2], bh[3]);
            }
        }

        // ---- online softmax over this j-half, score = -s
        float mt0 = -1e30f, mt1 = -1e30f;
#pragma unroll
        for (int n = 0; n < 4; n++) {
            mt0 = fmaxf(mt0, fmaxf(-s[n][0], -s[n][1]));
            mt1 = fmaxf(mt1, fmaxf(-s[n][2], -s[n][3]));
        }
        mt0 = fmaxf(mt0, __shfl_xor_sync(0xffffffffu, mt0, 1));
        mt0 = fmaxf(mt0, __shfl_xor_sync(0xffffffffu, mt0, 2));
        mt1 = fmaxf(mt1, __shfl_xor_sync(0xffffffffu, mt1, 1));
        mt1 = fmaxf(mt1, __shfl_xor_sync(0xffffffffu, mt1, 2));
        const float mn0 = fmaxf(m0, mt0), mn1 = fmaxf(m1, mt1);
        const float a0 = __expf(m0 - mn0), a1 = __expf(m1 - mn1);
        m0 = mn0; m1 = mn1;
        uint32_t ph[4][2], pl[4][2];
        float sum0 = 0.f, sum1 = 0.f;
#pragma unroll
        for (int n = 0; n < 4; n++) {
            float p00 = __expf(-s[n][0] - mn0), p01 = __expf(-s[n][1] - mn0);
            float p10 = __expf(-s[n][2] - mn1), p11 = __expf(-s[n][3] - mn1);
            sum0 += p00 + p01; sum1 += p10 + p11;
            uint32_t u00 = __float_as_uint(p00) & 0xffff0000u;
            uint32_t u01 = __float_as_uint(p01) & 0xffff0000u;
            uint32_t u10 = __float_as_uint(p10) & 0xffff0000u;
            uint32_t u11 = __float_as_uint(p11) & 0xffff0000u;
            ph[n][0] = u01 | (u00 >> 16);
            ph[n][1] = u11 | (u10 >> 16);
            pl[n][0] = pack_bf2(p00 - __uint_as_float(u00), p01 - __uint_as_float(u01));
            pl[n][1] = pack_bf2(p10 - __uint_as_float(u10), p11 - __uint_as_float(u11));
        }
        l0 = l0*a0 + sum0; l1 = l1*a1 + sum1;
#pragma unroll
        for (int n = 0; n < 8; n++) {
            o[n][0] *= a0; o[n][1] *= a0; o[n][2] *= a1; o[n][3] *= a1;
        }

        // ---- O += P.V over this warp's 32 j-rows (PhVh + PlVh + PhVl)
        {
            const int jadr = jhalf*32 + lane;
#pragma unroll
            for (int cn = 0; cn < 8; cn++) {
                uint32_t ad = kb + (uint32_t)(jadr*128) + (uint32_t)((cn*16) ^ ((jadr & 7)*16));
                uint32_t vh[4], vl[4];
                ldsm4t(vh, ad);
                ldsm4t(vl, ad + 8192u);
#pragma unroll
                for (int t = 0; t < 2; t++) {
                    uint32_t aH[4] = { ph[2*t][0], ph[2*t][1], ph[2*t+1][0], ph[2*t+1][1] };
                    uint32_t aL[4] = { pl[2*t][0], pl[2*t][1], pl[2*t+1][0], pl[2*t+1][1] };
                    mma(o[cn], aH, vh[2*t], vh[2*t+1]);
                    mma(o[cn], aL, vh[2*t], vh[2*t+1]);
                    mma(o[cn], aH, vl[2*t], vl[2*t+1]);
                }
            }
        }
        __syncthreads();
    }

    // ---- combine the two j-halves within the CTA
    l0 += __shfl_xor_sync(0xffffffffu, l0, 1);
    l0 += __shfl_xor_sync(0xffffffffu, l0, 2);
    l1 += __shfl_xor_sync(0xffffffffu, l1, 1);
    l1 += __shfl_xor_sync(0xffffffffu, l1, 2);
    const int r0 = wg*16 + g, r1 = r0 + 8;    // local rows 0..63
    if (lam == 0) {
        mex[jhalf][r0] = m0; lex[jhalf][r0] = l0;
        mex[jhalf][r1] = m1; lex[jhalf][r1] = l1;
    }
    __syncthreads();
    float mm0 = fmaxf(mex[0][r0], mex[1][r0]);
    float mm1 = fmaxf(mex[0][r1], mex[1][r1]);
    float Lt0 = lex[0][r0]*__expf(mex[0][r0]-mm0) + lex[1][r0]*__expf(mex[1][r0]-mm0);
    float Lt1 = lex[0][r1]*__expf(mex[0][r1]-mm1) + lex[1][r1]*__expf(mex[1][r1]-mm1);
    const float sc0 = __expf(m0 - mm0) / Lt0;
    const float sc1 = __expf(m1 - mm1) / Lt1;
    float* ob = reinterpret_cast<float*>(ks);   // 64 x 65 floats = 16.6 KB
    __syncthreads();                            // K-tile no longer needed
    if (jhalf == 0) {
#pragma unroll
        for (int cn = 0; cn < 8; cn++) {
            const int c0 = 8*cn + 2*lam;
            ob[r0*65 + c0]     = o[cn][0]*sc0;
            ob[r0*65 + c0 + 1] = o[cn][1]*sc0;
            ob[r1*65 + c0]     = o[cn][2]*sc1;
            ob[r1*65 + c0 + 1] = o[cn][3]*sc1;
        }
    }
    __syncthreads();
    if (jhalf == 1) {
#pragma unroll
        for (int cn = 0; cn < 8; cn++) {
            const int c0 = 8*cn + 2*lam;
            ob[r0*65 + c0]     += o[cn][0]*sc0;
            ob[r0*65 + c0 + 1] += o[cn][1]*sc0;
            ob[r1*65 + c0]     += o[cn][2]*sc1;
            ob[r1*65 + c0 + 1] += o[cn][3]*sc1;
        }
    }
    __syncthreads();
    const float gam = gp[0];
#pragma unroll
    for (int k = 0; k < 16; k++) {
        int idx = tid + k*256;          // 0..4095
        int c = idx >> 6, r = idx & 63;
        size_t oo = (size_t)(b*CH + c)*NPIX + i0 + r;
        out[oo] = gam*ob[r*65 + c] + g_y[oo];
    }
}

extern "C" void kernel_launch(void* const* d_in, const int* in_sizes, int n_in,
                              void* d_out, int out_size) {
    const float* x     = (const float*)d_in[0];
    const float* cw    = (const float*)d_in[1];
    const float* cb    = (const float*)d_in[2];
    const float* bns   = (const float*)d_in[3];
    const float* bnb   = (const float*)d_in[4];
    const float* pa    = (const float*)d_in[5];
    const float* gamma = (const float*)d_in[6];
    float* out = (float*)d_out;

    static bool done = false;
    if (!done) {
        cudaFuncSetAttribute(k_attn, cudaFuncAttributePreferredSharedMemoryCarveout, 100);
        done = true;
    }

    k_init_stats<<<1, 128>>>();
    k_conv<<<dim3(32, BATCH), 256>>>(x, cw, cb);
    k_bnt<<<dim3(64, BATCH), 256>>>(bns, bnb, pa);
    k_attn<<<dim3(64, BATCH), 256>>>(gamma, out);
}

// round 11
// speedup vs baseline: 1.0688x; 1.0199x over previous
#include <cuda_runtime.h>
#include <cuda_bf16.h>
#include <math.h>
#include <stdint.h>

#define BATCH 4
#define CH 64
#define NPIX 4096
#define NTOT (BATCH*CH*NPIX)

__device__ float g_y[NTOT];                // conv out -> normalized feat (B,C,N)
__device__ unsigned g_fh[BATCH*NPIX*32];   // hi bf16x2 (B,N,32)
__device__ unsigned g_fl[BATCH*NPIX*32];   // lo bf16x2
__device__ float g_stats[2*CH];

__device__ __forceinline__ uint32_t smem_u32(const void* p) {
    uint32_t a;
    asm("{ .reg .u64 t; cvta.to.shared.u64 t, %1; cvt.u32.u64 %0, t; }" : "=r"(a) : "l"(p));
    return a;
}
__device__ __forceinline__ void ldsm4(uint32_t* r, uint32_t a) {
    asm volatile("ldmatrix.sync.aligned.m8n8.x4.shared.b16 {%0,%1,%2,%3}, [%4];"
        : "=r"(r[0]), "=r"(r[1]), "=r"(r[2]), "=r"(r[3]) : "r"(a));
}
__device__ __forceinline__ void ldsm4t(uint32_t* r, uint32_t a) {
    asm volatile("ldmatrix.sync.aligned.m8n8.x4.trans.shared.b16 {%0,%1,%2,%3}, [%4];"
        : "=r"(r[0]), "=r"(r[1]), "=r"(r[2]), "=r"(r[3]) : "r"(a));
}
__device__ __forceinline__ void mma(float* d, const uint32_t* a, uint32_t b0, uint32_t b1) {
    asm volatile("mma.sync.aligned.m16n8k16.row.col.f32.bf16.bf16.f32 "
        "{%0,%1,%2,%3}, {%4,%5,%6,%7}, {%8,%9}, {%0,%1,%2,%3};"
        : "+f"(d[0]), "+f"(d[1]), "+f"(d[2]), "+f"(d[3])
        : "r"(a[0]), "r"(a[1]), "r"(a[2]), "r"(a[3]), "r"(b0), "r"(b1));
}
__device__ __forceinline__ uint32_t pack_bf2(float lo, float hi) {
    uint32_t d;
    asm("cvt.rn.bf16x2.f32 %0, %1, %2;" : "=r"(d) : "f"(hi), "f"(lo));
    return d;
}
__device__ __forceinline__ float ex2(float x) {
    float r;
    asm("ex2.approx.f32 %0, %1;" : "=f"(r) : "f"(x));
    return r;
}
#define GBAR(id) asm volatile("bar.sync %0, %1;" :: "r"(id), "r"(128) : "memory")

__global__ void k_init_stats() { int t = threadIdx.x; if (t < 2*CH) g_stats[t] = 0.0f; }

// -------- conv 3x3 + bias, 2 c_out per CTA (grid 128 = one wave) ----------
__global__ void __launch_bounds__(256) k_conv(const float* __restrict__ x,
                                              const float* __restrict__ w,
                                              const float* __restrict__ bvec) {
    __shared__ float xs[66*66];
    const int co0 = blockIdx.x*2, b = blockIdx.y, tid = threadIdx.x;
    for (int i = tid; i < 66*66; i += 256) xs[i] = 0.0f;
    float accA[4][4], accB[4][4];
#pragma unroll
    for (int s = 0; s < 4; s++)
#pragma unroll
        for (int e = 0; e < 4; e++) { accA[s][e]=0.f; accB[s][e]=0.f; }
    const float4* xb4 = reinterpret_cast<const float4*>(x + (size_t)b*CH*NPIX);
    for (int ci = 0; ci < CH; ci++) {
        __syncthreads();
#pragma unroll
        for (int k = 0; k < 4; k++) {
            int lin = tid + k*256;
            float4 v = xb4[ci*1024 + lin];
            float* dst = xs + ((lin>>4)+1)*66 + ((lin&15)<<2) + 1;
            dst[0]=v.x; dst[1]=v.y; dst[2]=v.z; dst[3]=v.w;
        }
        __syncthreads();
        const float* wA = w + (co0*CH + ci)*9;
        const float* wB = w + ((co0+1)*CH + ci)*9;
        float a0=wA[0],a1=wA[1],a2=wA[2],a3=wA[3],a4=wA[4],a5=wA[5],a6=wA[6],a7=wA[7],a8=wA[8];
        float b0=wB[0],b1=wB[1],b2=wB[2],b3=wB[3],b4=wB[4],b5=wB[5],b6=wB[6],b7=wB[7],b8=wB[8];
#pragma unroll
        for (int s = 0; s < 4; s++) {
            int pb = s*1024 + tid*4;
            const float* r0 = xs + (pb>>6)*66 + (pb&63);
            const float* r1 = r0 + 66; const float* r2 = r1 + 66;
            float t0,t1,t2,t3,t4,t5;
            t0=r0[0];t1=r0[1];t2=r0[2];t3=r0[3];t4=r0[4];t5=r0[5];
            accA[s][0]+=t0*a0+t1*a1+t2*a2; accA[s][1]+=t1*a0+t2*a1+t3*a2;
            accA[s][2]+=t2*a0+t3*a1+t4*a2; accA[s][3]+=t3*a0+t4*a1+t5*a2;
            accB[s][0]+=t0*b0+t1*b1+t2*b2; accB[s][1]+=t1*b0+t2*b1+t3*b2;
            accB[s][2]+=t2*b0+t3*b1+t4*b2; accB[s][3]+=t3*b0+t4*b1+t5*b2;
            t0=r1[0];t1=r1[1];t2=r1[2];t3=r1[3];t4=r1[4];t5=r1[5];
            accA[s][0]+=t0*a3+t1*a4+t2*a5; accA[s][1]+=t1*a3+t2*a4+t3*a5;
            accA[s][2]+=t2*a3+t3*a4+t4*a5; accA[s][3]+=t3*a3+t4*a4+t5*a5;
            accB[s][0]+=t0*b3+t1*b4+t2*b5; accB[s][1]+=t1*b3+t2*b4+t3*b5;
            accB[s][2]+=t2*b3+t3*b4+t4*b5; accB[s][3]+=t3*b3+t4*b4+t5*b5;
            t0=r2[0];t1=r2[1];t2=r2[2];t3=r2[3];t4=r2[4];t5=r2[5];
            accA[s][0]+=t0*a6+t1*a7+t2*a8; accA[s][1]+=t1*a6+t2*a7+t3*a8;
            accA[s][2]+=t2*a6+t3*a7+t4*a8; accA[s][3]+=t3*a6+t4*a7+t5*a8;
            accB[s][0]+=t0*b6+t1*b7+t2*b8; accB[s][1]+=t1*b6+t2*b7+t3*b8;
            accB[s][2]+=t2*b6+t3*b7+t4*b8; accB[s][3]+=t3*b6+t4*b7+t5*b8;
        }
    }
    float s1a=0.f, s2a=0.f, s1b=0.f, s2b=0.f;
    {
        const float cba = bvec[co0], cbb = bvec[co0+1];
        float4* ypA = reinterpret_cast<float4*>(g_y + (size_t)(b*CH + co0)*NPIX);
        float4* ypB = reinterpret_cast<float4*>(g_y + (size_t)(b*CH + co0 + 1)*NPIX);
#pragma unroll
        for (int s = 0; s < 4; s++) {
            float v0=accA[s][0]+cba, v1=accA[s][1]+cba, v2=accA[s][2]+cba, v3=accA[s][3]+cba;
            ypA[s*256 + tid] = make_float4(v0,v1,v2,v3);
            s1a += v0+v1+v2+v3; s2a += v0*v0+v1*v1+v2*v2+v3*v3;
            float u0=accB[s][0]+cbb, u1=accB[s][1]+cbb, u2=accB[s][2]+cbb, u3=accB[s][3]+cbb;
            ypB[s*256 + tid] = make_float4(u0,u1,u2,u3);
            s1b += u0+u1+u2+u3; s2b += u0*u0+u1*u1+u2*u2+u3*u3;
        }
    }
#pragma unroll
    for (int m = 16; m >= 1; m >>= 1) {
        s1a += __shfl_xor_sync(0xffffffffu, s1a, m);
        s2a += __shfl_xor_sync(0xffffffffu, s2a, m);
        s1b += __shfl_xor_sync(0xffffffffu, s1b, m);
        s2b += __shfl_xor_sync(0xffffffffu, s2b, m);
    }
    __syncthreads();
    if ((tid & 31) == 0) {
        int ww = tid>>5;
        xs[ww] = s1a; xs[8+ww] = s2a; xs[16+ww] = s1b; xs[24+ww] = s2b;
    }
    __syncthreads();
    if (tid == 0) {
        float r1a=0.f, r2a=0.f, r1b=0.f, r2b=0.f;
        for (int i = 0; i < 8; i++) { r1a+=xs[i]; r2a+=xs[8+i]; r1b+=xs[16+i]; r2b+=xs[24+i]; }
        atomicAdd(&g_stats[co0], r1a);      atomicAdd(&g_stats[CH+co0], r2a);
        atomicAdd(&g_stats[co0+1], r1b);    atomicAdd(&g_stats[CH+co0+1], r2b);
    }
}

// ------------- BN + PReLU; feat in-place; transposed split-bf16 out ---------
__global__ void __launch_bounds__(256) k_bnt(const float* __restrict__ scale,
                                             const float* __restrict__ bias,
                                             const float* __restrict__ pa) {
    __shared__ float t[64][65];
    __shared__ float msc[64], mof[64];
    const int b = blockIdx.y, i0 = blockIdx.x*64, tid = threadIdx.x;
    const float a = pa[0];
    if (tid < 64) {
        const float inv = 1.0f / (float)(BATCH*NPIX);
        float m = g_stats[tid]*inv, v = g_stats[CH+tid]*inv - m*m;
        float r = rsqrtf(v + 1e-5f);
        msc[tid] = r*scale[tid]; mof[tid] = bias[tid] - m*r*scale[tid];
    }
    __syncthreads();
#pragma unroll
    for (int k = 0; k < 16; k++) {
        int idx = tid + k*256, c = idx>>6, ii = idx&63;
        size_t o = (size_t)(b*CH + c)*NPIX + i0 + ii;
        float v = g_y[o]*msc[c] + mof[c];
        v = (v >= 0.f) ? v : a*v;
        g_y[o] = v; t[c][ii] = v;
    }
    __syncthreads();
#pragma unroll
    for (int k = 0; k < 8; k++) {
        int idx = tid + k*256, ii = idx>>5, cp = idx&31;
        float v0 = t[2*cp][ii], v1 = t[2*cp+1][ii];
        uint32_t u0 = __float_as_uint(v0), u1 = __float_as_uint(v1);
        uint32_t h0 = u0 & 0xffff0000u, h1 = u1 & 0xffff0000u;
        float r0 = v0 - __uint_as_float(h0), r1 = v1 - __uint_as_float(h1);
        size_t o = ((size_t)b*NPIX + i0 + ii)*32 + cp;
        g_fh[o] = h1 | (h0 >> 16);
        g_fl[o] = pack_bf2(r0, r1);
    }
}

// -- group (128 thr) stages its OWN 32x64 hi+lo half (4 cp.async/thread) ----
__device__ __forceinline__ void stg_g(uint32_t base, const unsigned* fh,
                                      const unsigned* fl, int j0, int jhalf, int gt) {
#pragma unroll
    for (int k = 0; k < 4; k++) {
        int idx = gt + k*128;                   // 0..511
        int hilo = idx >> 8;                    // 0: hi, 1: lo
        int rr = jhalf*32 + ((idx >> 3) & 31);
        int q = idx & 7;
        uint32_t dst = base + (uint32_t)hilo*8192u + (uint32_t)(rr*128) +
                       (uint32_t)((q*16) ^ ((rr & 7)*16));
        const unsigned* src = (hilo ? fl : fh) + (size_t)(j0 + rr)*32 + q*4;
        asm volatile("cp.async.cg.shared.global [%0], [%1], 16;" :: "r"(dst), "l"(src));
    }
    asm volatile("cp.async.commit_group;" ::: "memory");
}

// ---- flash attention: 64-row tile, 256 thr, 2 independent j-half groups ---
__global__ void __launch_bounds__(256, 2) k_attn(const float* __restrict__ gp,
                                                 float* __restrict__ out) {
    __shared__ __align__(1024) char ks[32768];   // 2 bufs x (hi 8K + lo 8K); reused as O-combine
    __shared__ float mex[2][64], lex[2][64];
    const uint32_t ksb = smem_u32(ks);
    const int tid = threadIdx.x, w = tid >> 5, lane = tid & 31;
    const int g = lane >> 2, lam = lane & 3;
    const int wg = w >> 1, jhalf = w & 1;
    const int gt = wg*32 + lane;                 // 0..127 within group
    const int it = blockIdx.x, b = blockIdx.y;
    const int i0 = it * 64;
    const int row0 = i0 + wg*16 + g, row1 = row0 + 8;
    const float L2E = 1.4426950408889634f;

    const unsigned* fh = g_fh + (size_t)b*NPIX*32;
    const unsigned* fl = g_fl + (size_t)b*NPIX*32;

    uint32_t qh[4][4], ql[4][4];
#pragma unroll
    for (int kc = 0; kc < 4; kc++) {
        qh[kc][0] = fh[(size_t)row0*32 + lam + 8*kc];
        qh[kc][1] = fh[(size_t)row1*32 + lam + 8*kc];
        qh[kc][2] = fh[(size_t)row0*32 + lam + 4 + 8*kc];
        qh[kc][3] = fh[(size_t)row1*32 + lam + 4 + 8*kc];
        ql[kc][0] = fl[(size_t)row0*32 + lam + 8*kc];
        ql[kc][1] = fl[(size_t)row1*32 + lam + 8*kc];
        ql[kc][2] = fl[(size_t)row0*32 + lam + 4 + 8*kc];
        ql[kc][3] = fl[(size_t)row1*32 + lam + 4 + 8*kc];
    }

    float o[8][4];
#pragma unroll
    for (int n = 0; n < 8; n++) { o[n][0]=o[n][1]=o[n][2]=o[n][3]=0.f; }
    float m0 = -1e30f, m1 = -1e30f, l0 = 0.f, l1 = 0.f;

    stg_g(ksb, fh, fl, 0, jhalf, gt);

    for (int jt = 0; jt < 64; jt++) {
        if (jt < 63) {
            stg_g(ksb + (uint32_t)(((jt+1)&1)*16384), fh, fl, (jt+1)*64, jhalf, gt);
            asm volatile("cp.async.wait_group 1;" ::: "memory");
        } else {
            asm volatile("cp.async.wait_group 0;" ::: "memory");
        }
        GBAR(1 + jhalf);                        // staging of jt visible group-wide
        const uint32_t kb = ksb + (uint32_t)((jt&1)*16384);

        // ---- S = Q.K^T over this warp's 32-col j-half (hh + hl + lh)
        float s[4][4];
#pragma unroll
        for (int n = 0; n < 4; n++) { s[n][0]=s[n][1]=s[n][2]=s[n][3]=0.f; }
#pragma unroll
        for (int jn2 = 0; jn2 < 2; jn2++) {
            const int jadr = jhalf*32 + 16*jn2 + (lane & 7) + ((lane >> 4) & 1)*8;
#pragma unroll
            for (int kc = 0; kc < 4; kc++) {
                const int q = 2*kc + ((lane >> 3) & 1);
                uint32_t ah = kb + (uint32_t)(jadr*128) + (uint32_t)((q*16) ^ ((jadr & 7)*16));
                uint32_t bh[4], bl[4];
                ldsm4(bh, ah);
                ldsm4(bl, ah + 8192u);
                mma(s[2*jn2],   qh[kc], bh[0], bh[1]);
                mma(s[2*jn2],   qh[kc], bl[0], bl[1]);
                mma(s[2*jn2],   ql[kc], bh[0], bh[1]);
                mma(s[2*jn2+1], qh[kc], bh[2], bh[3]);
                mma(s[2*jn2+1], qh[kc], bl[2], bl[3]);
                mma(s[2*jn2+1], ql[kc], bh[2], bh[3]);
            }
        }

        // ---- online softmax over this j-half, score = -s
        float mt0 = -1e30f, mt1 = -1e30f;
#pragma unroll
        for (int n = 0; n < 4; n++) {
            mt0 = fmaxf(mt0, fmaxf(-s[n][0], -s[n][1]));
            mt1 = fmaxf(mt1, fmaxf(-s[n][2], -s[n][3]));
        }
        mt0 = fmaxf(mt0, __shfl_xor_sync(0xffffffffu, mt0, 1));
        mt0 = fmaxf(mt0, __shfl_xor_sync(0xffffffffu, mt0, 2));
        mt1 = fmaxf(mt1, __shfl_xor_sync(0xffffffffu, mt1, 1));
        mt1 = fmaxf(mt1, __shfl_xor_sync(0xffffffffu, mt1, 2));
        const float mn0 = fmaxf(m0, mt0), mn1 = fmaxf(m1, mt1);
        const float a0 = ex2((m0 - mn0)*L2E), a1 = ex2((m1 - mn1)*L2E);
        const float nm0 = -mn0*L2E, nm1 = -mn1*L2E;
        const bool resc = !__all_sync(0xffffffffu, (mn0 == m0) & (mn1 == m1));
        m0 = mn0; m1 = mn1;
        uint32_t ph[4][2], pl[4][2];
        float sum0 = 0.f, sum1 = 0.f;
#pragma unroll
        for (int n = 0; n < 4; n++) {
            float p00 = ex2(fmaf(s[n][0], -L2E, nm0));
            float p01 = ex2(fmaf(s[n][1], -L2E, nm0));
            float p10 = ex2(fmaf(s[n][2], -L2E, nm1));
            float p11 = ex2(fmaf(s[n][3], -L2E, nm1));
            sum0 += p00 + p01; sum1 += p10 + p11;
            uint32_t u00 = __float_as_uint(p00) & 0xffff0000u;
            uint32_t u01 = __float_as_uint(p01) & 0xffff0000u;
            uint32_t u10 = __float_as_uint(p10) & 0xffff0000u;
            uint32_t u11 = __float_as_uint(p11) & 0xffff0000u;
            ph[n][0] = u01 | (u00 >> 16);
            ph[n][1] = u11 | (u10 >> 16);
            pl[n][0] = pack_bf2(p00 - __uint_as_float(u00), p01 - __uint_as_float(u01));
            pl[n][1] = pack_bf2(p10 - __uint_as_float(u10), p11 - __uint_as_float(u11));
        }
        l0 = l0*a0 + sum0; l1 = l1*a1 + sum1;
        if (resc) {
#pragma unroll
            for (int n = 0; n < 8; n++) {
                o[n][0] *= a0; o[n][1] *= a0; o[n][2] *= a1; o[n][3] *= a1;
            }
        }

        // ---- O += P.V over this warp's 32 j-rows (PhVh + PlVh + PhVl)
        {
            const int jadr = jhalf*32 + lane;
#pragma unroll
            for (int cn = 0; cn < 8; cn++) {
                uint32_t ad = kb + (uint32_t)(jadr*128) + (uint32_t)((cn*16) ^ ((jadr & 7)*16));
                uint32_t vh[4], vl[4];
                ldsm4t(vh, ad);
                ldsm4t(vl, ad + 8192u);
#pragma unroll
                for (int t = 0; t < 2; t++) {
                    uint32_t aH[4] = { ph[2*t][0], ph[2*t][1], ph[2*t+1][0], ph[2*t+1][1] };
                    uint32_t aL[4] = { pl[2*t][0], pl[2*t][1], pl[2*t+1][0], pl[2*t+1][1] };
                    mma(o[cn], aH, vh[2*t], vh[2*t+1]);
                    mma(o[cn], aL, vh[2*t], vh[2*t+1]);
                    mma(o[cn], aH, vl[2*t], vl[2*t+1]);
                }
            }
        }
        GBAR(1 + jhalf);                        // group done reading jt's buffer
    }

    // ---- combine the two j-halves within the CTA
    l0 += __shfl_xor_sync(0xffffffffu, l0, 1);
    l0 += __shfl_xor_sync(0xffffffffu, l0, 2);
    l1 += __shfl_xor_sync(0xffffffffu, l1, 1);
    l1 += __shfl_xor_sync(0xffffffffu, l1, 2);
    const int r0 = wg*16 + g, r1 = r0 + 8;    // local rows 0..63
    if (lam == 0) {
        mex[jhalf][r0] = m0; lex[jhalf][r0] = l0;
        mex[jhalf][r1] = m1; lex[jhalf][r1] = l1;
    }
    __syncthreads();
    float mm0 = fmaxf(mex[0][r0], mex[1][r0]);
    float mm1 = fmaxf(mex[0][r1], mex[1][r1]);
    float Lt0 = lex[0][r0]*ex2((mex[0][r0]-mm0)*L2E) + lex[1][r0]*ex2((mex[1][r0]-mm0)*L2E);
    float Lt1 = lex[0][r1]*ex2((mex[0][r1]-mm1)*L2E) + lex[1][r1]*ex2((mex[1][r1]-mm1)*L2E);
    const float sc0 = ex2((m0 - mm0)*L2E) / Lt0;
    const float sc1 = ex2((m1 - mm1)*L2E) / Lt1;
    float* ob = reinterpret_cast<float*>(ks);   // 64 x 65 floats = 16.6 KB
    __syncthreads();                            // K-tile no longer needed
    if (jhalf == 0) {
#pragma unroll
        for (int cn = 0; cn < 8; cn++) {
            const int c0 = 8*cn + 2*lam;
            ob[r0*65 + c0]     = o[cn][0]*sc0;
            ob[r0*65 + c0 + 1] = o[cn][1]*sc0;
            ob[r1*65 + c0]     = o[cn][2]*sc1;
            ob[r1*65 + c0 + 1] = o[cn][3]*sc1;
        }
    }
    __syncthreads();
    if (jhalf == 1) {
#pragma unroll
        for (int cn = 0; cn < 8; cn++) {
            const int c0 = 8*cn + 2*lam;
            ob[r0*65 + c0]     += o[cn][0]*sc0;
            ob[r0*65 + c0 + 1] += o[cn][1]*sc0;
            ob[r1*65 + c0]     += o[cn][2]*sc1;
            ob[r1*65 + c0 + 1] += o[cn][3]*sc1;
        }
    }
    __syncthreads();
    const float gam = gp[0];
#pragma unroll
    for (int k = 0; k < 16; k++) {
        int idx = tid + k*256;          // 0..4095
        int c = idx >> 6, r = idx & 63;
        size_t oo = (size_t)(b*CH + c)*NPIX + i0 + r;
        out[oo] = gam*ob[r*65 + c] + g_y[oo];
    }
}

extern "C" void kernel_launch(void* const* d_in, const int* in_sizes, int n_in,
                              void* d_out, int out_size) {
    const float* x     = (const float*)d_in[0];
    const float* cw    = (const float*)d_in[1];
    const float* cb    = (const float*)d_in[2];
    const float* bns   = (const float*)d_in[3];
    const float* bnb   = (const float*)d_in[4];
    const float* pa    = (const float*)d_in[5];
    const float* gamma = (const float*)d_in[6];
    float* out = (float*)d_out;

    static bool done = false;
    if (!done) {
        cudaFuncSetAttribute(k_attn, cudaFuncAttributePreferredSharedMemoryCarveout, 100);
        done = true;
    }

    k_init_stats<<<1, 128>>>();
    k_conv<<<dim3(32, BATCH), 256>>>(x, cw, cb);
    k_bnt<<<dim3(64, BATCH), 256>>>(bns, bnb, pa);
    k_attn<<<dim3(64, BATCH), 256>>>(gamma, out);
}

// round 12
// speedup vs baseline: 1.0863x; 1.0164x over previous
#include <cuda_runtime.h>
#include <cuda_bf16.h>
#include <math.h>
#include <stdint.h>

#define BATCH 4
#define CH 64
#define NPIX 4096
#define NTOT (BATCH*CH*NPIX)

__device__ float g_y[NTOT];                // conv out -> normalized feat (B,C,N)
__device__ unsigned g_fh[BATCH*NPIX*32];   // hi bf16x2 (B,N,32)
__device__ unsigned g_fl[BATCH*NPIX*32];   // lo bf16x2
__device__ float g_stats[2*CH];

__device__ __forceinline__ uint32_t smem_u32(const void* p) {
    uint32_t a;
    asm("{ .reg .u64 t; cvta.to.shared.u64 t, %1; cvt.u32.u64 %0, t; }" : "=r"(a) : "l"(p));
    return a;
}
__device__ __forceinline__ void ldsm4(uint32_t* r, uint32_t a) {
    asm volatile("ldmatrix.sync.aligned.m8n8.x4.shared.b16 {%0,%1,%2,%3}, [%4];"
        : "=r"(r[0]), "=r"(r[1]), "=r"(r[2]), "=r"(r[3]) : "r"(a));
}
__device__ __forceinline__ void ldsm4t(uint32_t* r, uint32_t a) {
    asm volatile("ldmatrix.sync.aligned.m8n8.x4.trans.shared.b16 {%0,%1,%2,%3}, [%4];"
        : "=r"(r[0]), "=r"(r[1]), "=r"(r[2]), "=r"(r[3]) : "r"(a));
}
__device__ __forceinline__ void mma(float* d, const uint32_t* a, uint32_t b0, uint32_t b1) {
    asm volatile("mma.sync.aligned.m16n8k16.row.col.f32.bf16.bf16.f32 "
        "{%0,%1,%2,%3}, {%4,%5,%6,%7}, {%8,%9}, {%0,%1,%2,%3};"
        : "+f"(d[0]), "+f"(d[1]), "+f"(d[2]), "+f"(d[3])
        : "r"(a[0]), "r"(a[1]), "r"(a[2]), "r"(a[3]), "r"(b0), "r"(b1));
}
__device__ __forceinline__ uint32_t pack_bf2(float lo, float hi) {
    uint32_t d;
    asm("cvt.rn.bf16x2.f32 %0, %1, %2;" : "=r"(d) : "f"(hi), "f"(lo));
    return d;
}
__device__ __forceinline__ float ex2(float x) {
    float r;
    asm("ex2.approx.f32 %0, %1;" : "=f"(r) : "f"(x));
    return r;
}
#define GBAR(id) asm volatile("bar.sync %0, %1;" :: "r"(id), "r"(128) : "memory")

__global__ void k_init_stats() { int t = threadIdx.x; if (t < 2*CH) g_stats[t] = 0.0f; }

// -------- conv 3x3 + bias, 2 c_out per CTA (grid 128 = one wave) ----------
__global__ void __launch_bounds__(256) k_conv(const float* __restrict__ x,
                                              const float* __restrict__ w,
                                              const float* __restrict__ bvec) {
    __shared__ float xs[66*66];
    const int co0 = blockIdx.x*2, b = blockIdx.y, tid = threadIdx.x;
    for (int i = tid; i < 66*66; i += 256) xs[i] = 0.0f;
    float accA[4][4], accB[4][4];
#pragma unroll
    for (int s = 0; s < 4; s++)
#pragma unroll
        for (int e = 0; e < 4; e++) { accA[s][e]=0.f; accB[s][e]=0.f; }
    const float4* xb4 = reinterpret_cast<const float4*>(x + (size_t)b*CH*NPIX);
    for (int ci = 0; ci < CH; ci++) {
        __syncthreads();
#pragma unroll
        for (int k = 0; k < 4; k++) {
            int lin = tid + k*256;
            float4 v = xb4[ci*1024 + lin];
            float* dst = xs + ((lin>>4)+1)*66 + ((lin&15)<<2) + 1;
            dst[0]=v.x; dst[1]=v.y; dst[2]=v.z; dst[3]=v.w;
        }
        __syncthreads();
        const float* wA = w + (co0*CH + ci)*9;
        const float* wB = w + ((co0+1)*CH + ci)*9;
        float a0=wA[0],a1=wA[1],a2=wA[2],a3=wA[3],a4=wA[4],a5=wA[5],a6=wA[6],a7=wA[7],a8=wA[8];
        float b0=wB[0],b1=wB[1],b2=wB[2],b3=wB[3],b4=wB[4],b5=wB[5],b6=wB[6],b7=wB[7],b8=wB[8];
#pragma unroll
        for (int s = 0; s < 4; s++) {
            int pb = s*1024 + tid*4;
            const float* r0 = xs + (pb>>6)*66 + (pb&63);
            const float* r1 = r0 + 66; const float* r2 = r1 + 66;
            float t0,t1,t2,t3,t4,t5;
            t0=r0[0];t1=r0[1];t2=r0[2];t3=r0[3];t4=r0[4];t5=r0[5];
            accA[s][0]+=t0*a0+t1*a1+t2*a2; accA[s][1]+=t1*a0+t2*a1+t3*a2;
            accA[s][2]+=t2*a0+t3*a1+t4*a2; accA[s][3]+=t3*a0+t4*a1+t5*a2;
            accB[s][0]+=t0*b0+t1*b1+t2*b2; accB[s][1]+=t1*b0+t2*b1+t3*b2;
            accB[s][2]+=t2*b0+t3*b1+t4*b2; accB[s][3]+=t3*b0+t4*b1+t5*b2;
            t0=r1[0];t1=r1[1];t2=r1[2];t3=r1[3];t4=r1[4];t5=r1[5];
            accA[s][0]+=t0*a3+t1*a4+t2*a5; accA[s][1]+=t1*a3+t2*a4+t3*a5;
            accA[s][2]+=t2*a3+t3*a4+t4*a5; accA[s][3]+=t3*a3+t4*a4+t5*a5;
            accB[s][0]+=t0*b3+t1*b4+t2*b5; accB[s][1]+=t1*b3+t2*b4+t3*b5;
            accB[s][2]+=t2*b3+t3*b4+t4*b5; accB[s][3]+=t3*b3+t4*b4+t5*b5;
            t0=r2[0];t1=r2[1];t2=r2[2];t3=r2[3];t4=r2[4];t5=r2[5];
            accA[s][0]+=t0*a6+t1*a7+t2*a8; accA[s][1]+=t1*a6+t2*a7+t3*a8;
            accA[s][2]+=t2*a6+t3*a7+t4*a8; accA[s][3]+=t3*a6+t4*a7+t5*a8;
            accB[s][0]+=t0*b6+t1*b7+t2*b8; accB[s][1]+=t1*b6+t2*b7+t3*b8;
            accB[s][2]+=t2*b6+t3*b7+t4*b8; accB[s][3]+=t3*b6+t4*b7+t5*b8;
        }
    }
    float s1a=0.f, s2a=0.f, s1b=0.f, s2b=0.f;
    {
        const float cba = bvec[co0], cbb = bvec[co0+1];
        float4* ypA = reinterpret_cast<float4*>(g_y + (size_t)(b*CH + co0)*NPIX);
        float4* ypB = reinterpret_cast<float4*>(g_y + (size_t)(b*CH + co0 + 1)*NPIX);
#pragma unroll
        for (int s = 0; s < 4; s++) {
            float v0=accA[s][0]+cba, v1=accA[s][1]+cba, v2=accA[s][2]+cba, v3=accA[s][3]+cba;
            ypA[s*256 + tid] = make_float4(v0,v1,v2,v3);
            s1a += v0+v1+v2+v3; s2a += v0*v0+v1*v1+v2*v2+v3*v3;
            float u0=accB[s][0]+cbb, u1=accB[s][1]+cbb, u2=accB[s][2]+cbb, u3=accB[s][3]+cbb;
            ypB[s*256 + tid] = make_float4(u0,u1,u2,u3);
            s1b += u0+u1+u2+u3; s2b += u0*u0+u1*u1+u2*u2+u3*u3;
        }
    }
#pragma unroll
    for (int m = 16; m >= 1; m >>= 1) {
        s1a += __shfl_xor_sync(0xffffffffu, s1a, m);
        s2a += __shfl_xor_sync(0xffffffffu, s2a, m);
        s1b += __shfl_xor_sync(0xffffffffu, s1b, m);
        s2b += __shfl_xor_sync(0xffffffffu, s2b, m);
    }
    __syncthreads();
    if ((tid & 31) == 0) {
        int ww = tid>>5;
        xs[ww] = s1a; xs[8+ww] = s2a; xs[16+ww] = s1b; xs[24+ww] = s2b;
    }
    __syncthreads();
    if (tid == 0) {
        float r1a=0.f, r2a=0.f, r1b=0.f, r2b=0.f;
        for (int i = 0; i < 8; i++) { r1a+=xs[i]; r2a+=xs[8+i]; r1b+=xs[16+i]; r2b+=xs[24+i]; }
        atomicAdd(&g_stats[co0], r1a);      atomicAdd(&g_stats[CH+co0], r2a);
        atomicAdd(&g_stats[co0+1], r1b);    atomicAdd(&g_stats[CH+co0+1], r2b);
    }
}

// ------------- BN + PReLU; feat in-place; transposed split-bf16 out ---------
__global__ void __launch_bounds__(256) k_bnt(const float* __restrict__ scale,
                                             const float* __restrict__ bias,
                                             const float* __restrict__ pa) {
    __shared__ float t[64][65];
    __shared__ float msc[64], mof[64];
    const int b = blockIdx.y, i0 = blockIdx.x*64, tid = threadIdx.x;
    const float a = pa[0];
    if (tid < 64) {
        const float inv = 1.0f / (float)(BATCH*NPIX);
        float m = g_stats[tid]*inv, v = g_stats[CH+tid]*inv - m*m;
        float r = rsqrtf(v + 1e-5f);
        msc[tid] = r*scale[tid]; mof[tid] = bias[tid] - m*r*scale[tid];
    }
    __syncthreads();
#pragma unroll
    for (int k = 0; k < 16; k++) {
        int idx = tid + k*256, c = idx>>6, ii = idx&63;
        size_t o = (size_t)(b*CH + c)*NPIX + i0 + ii;
        float v = g_y[o]*msc[c] + mof[c];
        v = (v >= 0.f) ? v : a*v;
        g_y[o] = v; t[c][ii] = v;
    }
    __syncthreads();
#pragma unroll
    for (int k = 0; k < 8; k++) {
        int idx = tid + k*256, ii = idx>>5, cp = idx&31;
        float v0 = t[2*cp][ii], v1 = t[2*cp+1][ii];
        uint32_t u0 = __float_as_uint(v0), u1 = __float_as_uint(v1);
        uint32_t h0 = u0 & 0xffff0000u, h1 = u1 & 0xffff0000u;
        float r0 = v0 - __uint_as_float(h0), r1 = v1 - __uint_as_float(h1);
        size_t o = ((size_t)b*NPIX + i0 + ii)*32 + cp;
        g_fh[o] = h1 | (h0 >> 16);
        g_fl[o] = pack_bf2(r0, r1);
    }
}

// -- group (128 thr) stages its OWN 32x64 hi+lo half (4 cp.async/thread) ----
__device__ __forceinline__ void stg_g(uint32_t base, const unsigned* fh,
                                      const unsigned* fl, int j0, int jhalf, int gt) {
#pragma unroll
    for (int k = 0; k < 4; k++) {
        int idx = gt + k*128;                   // 0..511
        int hilo = idx >> 8;                    // 0: hi, 1: lo
        int rr = jhalf*32 + ((idx >> 3) & 31);
        int q = idx & 7;
        uint32_t dst = base + (uint32_t)hilo*8192u + (uint32_t)(rr*128) +
                       (uint32_t)((q*16) ^ ((rr & 7)*16));
        const unsigned* src = (hilo ? fl : fh) + (size_t)(j0 + rr)*32 + q*4;
        asm volatile("cp.async.cg.shared.global [%0], [%1], 16;" :: "r"(dst), "l"(src));
    }
    asm volatile("cp.async.commit_group;" ::: "memory");
}

// ---- flash attention: 64-row tile, 256 thr, 2 independent j-half groups ---
// Group split is warps {0-3} vs {4-7} so each SMSP (wid%4) holds one warp of
// EACH group -> one group's MMAs fill the other's softmax bubbles.
__global__ void __launch_bounds__(256, 2) k_attn(const float* __restrict__ gp,
                                                 float* __restrict__ out) {
    __shared__ __align__(1024) char ks[32768];   // 2 bufs x (hi 8K + lo 8K); reused as O-combine
    __shared__ float mex[2][64], lex[2][64];
    const uint32_t ksb = smem_u32(ks);
    const int tid = threadIdx.x, w = tid >> 5, lane = tid & 31;
    const int g = lane >> 2, lam = lane & 3;
    const int wg = w & 3, jhalf = w >> 2;        // <-- SMSP-interleaved groups
    const int gt = wg*32 + lane;                 // 0..127 within group
    const int it = blockIdx.x, b = blockIdx.y;
    const int i0 = it * 64;
    const int row0 = i0 + wg*16 + g, row1 = row0 + 8;
    const float L2E = 1.4426950408889634f;

    const unsigned* fh = g_fh + (size_t)b*NPIX*32;
    const unsigned* fl = g_fl + (size_t)b*NPIX*32;

    uint32_t qh[4][4], ql[4][4];
#pragma unroll
    for (int kc = 0; kc < 4; kc++) {
        qh[kc][0] = fh[(size_t)row0*32 + lam + 8*kc];
        qh[kc][1] = fh[(size_t)row1*32 + lam + 8*kc];
        qh[kc][2] = fh[(size_t)row0*32 + lam + 4 + 8*kc];
        qh[kc][3] = fh[(size_t)row1*32 + lam + 4 + 8*kc];
        ql[kc][0] = fl[(size_t)row0*32 + lam + 8*kc];
        ql[kc][1] = fl[(size_t)row1*32 + lam + 8*kc];
        ql[kc][2] = fl[(size_t)row0*32 + lam + 4 + 8*kc];
        ql[kc][3] = fl[(size_t)row1*32 + lam + 4 + 8*kc];
    }

    float o[8][4];
#pragma unroll
    for (int n = 0; n < 8; n++) { o[n][0]=o[n][1]=o[n][2]=o[n][3]=0.f; }
    float m0 = -1e30f, m1 = -1e30f, l0 = 0.f, l1 = 0.f;

    stg_g(ksb, fh, fl, 0, jhalf, gt);

    for (int jt = 0; jt < 64; jt++) {
        if (jt < 63) {
            stg_g(ksb + (uint32_t)(((jt+1)&1)*16384), fh, fl, (jt+1)*64, jhalf, gt);
            asm volatile("cp.async.wait_group 1;" ::: "memory");
        } else {
            asm volatile("cp.async.wait_group 0;" ::: "memory");
        }
        GBAR(1 + jhalf);                        // staging of jt visible group-wide
        const uint32_t kb = ksb + (uint32_t)((jt&1)*16384);

        // ---- S = Q.K^T over this warp's 32-col j-half (hh + hl + lh)
        float s[4][4];
#pragma unroll
        for (int n = 0; n < 4; n++) { s[n][0]=s[n][1]=s[n][2]=s[n][3]=0.f; }
#pragma unroll
        for (int jn2 = 0; jn2 < 2; jn2++) {
            const int jadr = jhalf*32 + 16*jn2 + (lane & 7) + ((lane >> 4) & 1)*8;
#pragma unroll
            for (int kc = 0; kc < 4; kc++) {
                const int q = 2*kc + ((lane >> 3) & 1);
                uint32_t ah = kb + (uint32_t)(jadr*128) + (uint32_t)((q*16) ^ ((jadr & 7)*16));
                uint32_t bh[4], bl[4];
                ldsm4(bh, ah);
                ldsm4(bl, ah + 8192u);
                mma(s[2*jn2],   qh[kc], bh[0], bh[1]);
                mma(s[2*jn2],   qh[kc], bl[0], bl[1]);
                mma(s[2*jn2],   ql[kc], bh[0], bh[1]);
                mma(s[2*jn2+1], qh[kc], bh[2], bh[3]);
                mma(s[2*jn2+1], qh[kc], bl[2], bl[3]);
                mma(s[2*jn2+1], ql[kc], bh[2], bh[3]);
            }
        }

        // ---- online softmax over this j-half, score = -s
        float mt0 = -1e30f, mt1 = -1e30f;
#pragma unroll
        for (int n = 0; n < 4; n++) {
            mt0 = fmaxf(mt0, fmaxf(-s[n][0], -s[n][1]));
            mt1 = fmaxf(mt1, fmaxf(-s[n][2], -s[n][3]));
        }
        mt0 = fmaxf(mt0, __shfl_xor_sync(0xffffffffu, mt0, 1));
        mt0 = fmaxf(mt0, __shfl_xor_sync(0xffffffffu, mt0, 2));
        mt1 = fmaxf(mt1, __shfl_xor_sync(0xffffffffu, mt1, 1));
        mt1 = fmaxf(mt1, __shfl_xor_sync(0xffffffffu, mt1, 2));
        const float mn0 = fmaxf(m0, mt0), mn1 = fmaxf(m1, mt1);
        const float a0 = ex2((m0 - mn0)*L2E), a1 = ex2((m1 - mn1)*L2E);
        const float nm0 = -mn0*L2E, nm1 = -mn1*L2E;
        const bool resc = !__all_sync(0xffffffffu, (mn0 == m0) & (mn1 == m1));
        m0 = mn0; m1 = mn1;
        uint32_t ph[4][2], pl[4][2];
        float sum0 = 0.f, sum1 = 0.f;
#pragma unroll
        for (int n = 0; n < 4; n++) {
            float p00 = ex2(fmaf(s[n][0], -L2E, nm0));
            float p01 = ex2(fmaf(s[n][1], -L2E, nm0));
            float p10 = ex2(fmaf(s[n][2], -L2E, nm1));
            float p11 = ex2(fmaf(s[n][3], -L2E, nm1));
            sum0 += p00 + p01; sum1 += p10 + p11;
            uint32_t u00 = __float_as_uint(p00) & 0xffff0000u;
            uint32_t u01 = __float_as_uint(p01) & 0xffff0000u;
            uint32_t u10 = __float_as_uint(p10) & 0xffff0000u;
            uint32_t u11 = __float_as_uint(p11) & 0xffff0000u;
            ph[n][0] = u01 | (u00 >> 16);
            ph[n][1] = u11 | (u10 >> 16);
            pl[n][0] = pack_bf2(p00 - __uint_as_float(u00), p01 - __uint_as_float(u01));
            pl[n][1] = pack_bf2(p10 - __uint_as_float(u10), p11 - __uint_as_float(u11));
        }
        l0 = l0*a0 + sum0; l1 = l1*a1 + sum1;
        if (resc) {
#pragma unroll
            for (int n = 0; n < 8; n++) {
                o[n][0] *= a0; o[n][1] *= a0; o[n][2] *= a1; o[n][3] *= a1;
            }
        }

        // ---- O += P.V over this warp's 32 j-rows (PhVh + PlVh + PhVl)
        {
            const int jadr = jhalf*32 + lane;
#pragma unroll
            for (int cn = 0; cn < 8; cn++) {
                uint32_t ad = kb + (uint32_t)(jadr*128) + (uint32_t)((cn*16) ^ ((jadr & 7)*16));
                uint32_t vh[4], vl[4];
                ldsm4t(vh, ad);
                ldsm4t(vl, ad + 8192u);
#pragma unroll
                for (int t = 0; t < 2; t++) {
                    uint32_t aH[4] = { ph[2*t][0], ph[2*t][1], ph[2*t+1][0], ph[2*t+1][1] };
                    uint32_t aL[4] = { pl[2*t][0], pl[2*t][1], pl[2*t+1][0], pl[2*t+1][1] };
                    mma(o[cn], aH, vh[2*t], vh[2*t+1]);
                    mma(o[cn], aL, vh[2*t], vh[2*t+1]);
                    mma(o[cn], aH, vl[2*t], vl[2*t+1]);
                }
            }
        }
        GBAR(1 + jhalf);                        // group done reading jt's buffer
    }

    // ---- combine the two j-halves within the CTA
    l0 += __shfl_xor_sync(0xffffffffu, l0, 1);
    l0 += __shfl_xor_sync(0xffffffffu, l0, 2);
    l1 += __shfl_xor_sync(0xffffffffu, l1, 1);
    l1 += __shfl_xor_sync(0xffffffffu, l1, 2);
    const int r0 = wg*16 + g, r1 = r0 + 8;    // local rows 0..63
    if (lam == 0) {
        mex[jhalf][r0] = m0; lex[jhalf][r0] = l0;
        mex[jhalf][r1] = m1; lex[jhalf][r1] = l1;
    }
    __syncthreads();
    float mm0 = fmaxf(mex[0][r0], mex[1][r0]);
    float mm1 = fmaxf(mex[0][r1], mex[1][r1]);
    float Lt0 = lex[0][r0]*ex2((mex[0][r0]-mm0)*L2E) + lex[1][r0]*ex2((mex[1][r0]-mm0)*L2E);
    float Lt1 = lex[0][r1]*ex2((mex[0][r1]-mm1)*L2E) + lex[1][r1]*ex2((mex[1][r1]-mm1)*L2E);
    const float sc0 = ex2((m0 - mm0)*L2E) / Lt0;
    const float sc1 = ex2((m1 - mm1)*L2E) / Lt1;
    float* ob = reinterpret_cast<float*>(ks);   // 64 x 65 floats = 16.6 KB
    __syncthreads();                            // K-tile no longer needed
    if (jhalf == 0) {
#pragma unroll
        for (int cn = 0; cn < 8; cn++) {
            const int c0 = 8*cn + 2*lam;
            ob[r0*65 + c0]     = o[cn][0]*sc0;
            ob[r0*65 + c0 + 1] = o[cn][1]*sc0;
            ob[r1*65 + c0]     = o[cn][2]*sc1;
            ob[r1*65 + c0 + 1] = o[cn][3]*sc1;
        }
    }
    __syncthreads();
    if (jhalf == 1) {
#pragma unroll
        for (int cn = 0; cn < 8; cn++) {
            const int c0 = 8*cn + 2*lam;
            ob[r0*65 + c0]     += o[cn][0]*sc0;
            ob[r0*65 + c0 + 1] += o[cn][1]*sc0;
            ob[r1*65 + c0]     += o[cn][2]*sc1;
            ob[r1*65 + c0 + 1] += o[cn][3]*sc1;
        }
    }
    __syncthreads();
    const float gam = gp[0];
#pragma unroll
    for (int k = 0; k < 16; k++) {
        int idx = tid + k*256;          // 0..4095
        int c = idx >> 6, r = idx & 63;
        size_t oo = (size_t)(b*CH + c)*NPIX + i0 + r;
        out[oo] = gam*ob[r*65 + c] + g_y[oo];
    }
}

extern "C" void kernel_launch(void* const* d_in, const int* in_sizes, int n_in,
                              void* d_out, int out_size) {
    const float* x     = (const float*)d_in[0];
    const float* cw    = (const float*)d_in[1];
    const float* cb    = (const float*)d_in[2];
    const float* bns   = (const float*)d_in[3];
    const float* bnb   = (const float*)d_in[4];
    const float* pa    = (const float*)d_in[5];
    const float* gamma = (const float*)d_in[6];
    float* out = (float*)d_out;

    static bool done = false;
    if (!done) {
        cudaFuncSetAttribute(k_attn, cudaFuncAttributePreferredSharedMemoryCarveout, 100);
        done = true;
    }

    k_init_stats<<<1, 128>>>();
    k_conv<<<dim3(32, BATCH), 256>>>(x, cw, cb);
    k_bnt<<<dim3(64, BATCH), 256>>>(bns, bnb, pa);
    k_attn<<<dim3(64, BATCH), 256>>>(gamma, out);
}

// round 15
// speedup vs baseline: 1.1796x; 1.0859x over previous
#include <cuda_runtime.h>
#include <cuda_bf16.h>
#include <math.h>
#include <stdint.h>

#define BATCH 4
#define CH 64
#define NPIX 4096
#define NTOT (BATCH*CH*NPIX)

__device__ float g_y[NTOT];                // conv out -> normalized feat (B,C,N)
__device__ unsigned g_fh[BATCH*NPIX*32];   // hi bf16x2 (B,N,32)  (RN)
__device__ unsigned g_fl[BATCH*NPIX*32];   // lo bf16x2 (RN residual)
__device__ float g_stats[2*CH];

__device__ __forceinline__ uint32_t smem_u32(const void* p) {
    uint32_t a;
    asm("{ .reg .u64 t; cvta.to.shared.u64 t, %1; cvt.u32.u64 %0, t; }" : "=r"(a) : "l"(p));
    return a;
}
__device__ __forceinline__ void ldsm4(uint32_t* r, uint32_t a) {
    asm volatile("ldmatrix.sync.aligned.m8n8.x4.shared.b16 {%0,%1,%2,%3}, [%4];"
        : "=r"(r[0]), "=r"(r[1]), "=r"(r[2]), "=r"(r[3]) : "r"(a));
}
__device__ __forceinline__ void ldsm4t(uint32_t* r, uint32_t a) {
    asm volatile("ldmatrix.sync.aligned.m8n8.x4.trans.shared.b16 {%0,%1,%2,%3}, [%4];"
        : "=r"(r[0]), "=r"(r[1]), "=r"(r[2]), "=r"(r[3]) : "r"(a));
}
__device__ __forceinline__ void mma(float* d, const uint32_t* a, uint32_t b0, uint32_t b1) {
    asm volatile("mma.sync.aligned.m16n8k16.row.col.f32.bf16.bf16.f32 "
        "{%0,%1,%2,%3}, {%4,%5,%6,%7}, {%8,%9}, {%0,%1,%2,%3};"
        : "+f"(d[0]), "+f"(d[1]), "+f"(d[2]), "+f"(d[3])
        : "r"(a[0]), "r"(a[1]), "r"(a[2]), "r"(a[3]), "r"(b0), "r"(b1));
}
__device__ __forceinline__ uint32_t pack_bf2(float lo, float hi) {
    uint32_t d;
    asm("cvt.rn.bf16x2.f32 %0, %1, %2;" : "=r"(d) : "f"(hi), "f"(lo));
    return d;
}
__device__ __forceinline__ float ex2(float x) {
    float r;
    asm("ex2.approx.f32 %0, %1;" : "=f"(r) : "f"(x));
    return r;
}
#define GBAR(id) asm volatile("bar.sync %0, %1;" :: "r"(id), "r"(128) : "memory")

__global__ void k_init_stats() { int t = threadIdx.x; if (t < 2*CH) g_stats[t] = 0.0f; }

// -------- conv 3x3 + bias, 2 c_out per CTA (grid 128 = one wave) ----------
__global__ void __launch_bounds__(256) k_conv(const float* __restrict__ x,
                                              const float* __restrict__ w,
                                              const float* __restrict__ bvec) {
    __shared__ float xs[66*66];
    const int co0 = blockIdx.x*2, b = blockIdx.y, tid = threadIdx.x;
    for (int i = tid; i < 66*66; i += 256) xs[i] = 0.0f;
    float accA[4][4], accB[4][4];
#pragma unroll
    for (int s = 0; s < 4; s++)
#pragma unroll
        for (int e = 0; e < 4; e++) { accA[s][e]=0.f; accB[s][e]=0.f; }
    const float4* xb4 = reinterpret_cast<const float4*>(x + (size_t)b*CH*NPIX);
    for (int ci = 0; ci < CH; ci++) {
        __syncthreads();
#pragma unroll
        for (int k = 0; k < 4; k++) {
            int lin = tid + k*256;
            float4 v = xb4[ci*1024 + lin];
            float* dst = xs + ((lin>>4)+1)*66 + ((lin&15)<<2) + 1;
            dst[0]=v.x; dst[1]=v.y; dst[2]=v.z; dst[3]=v.w;
        }
        __syncthreads();
        const float* wA = w + (co0*CH + ci)*9;
        const float* wB = w + ((co0+1)*CH + ci)*9;
        float a0=wA[0],a1=wA[1],a2=wA[2],a3=wA[3],a4=wA[4],a5=wA[5],a6=wA[6],a7=wA[7],a8=wA[8];
        float b0=wB[0],b1=wB[1],b2=wB[2],b3=wB[3],b4=wB[4],b5=wB[5],b6=wB[6],b7=wB[7],b8=wB[8];
#pragma unroll
        for (int s = 0; s < 4; s++) {
            int pb = s*1024 + tid*4;
            const float* r0 = xs + (pb>>6)*66 + (pb&63);
            const float* r1 = r0 + 66; const float* r2 = r1 + 66;
            float t0,t1,t2,t3,t4,t5;
            t0=r0[0];t1=r0[1];t2=r0[2];t3=r0[3];t4=r0[4];t5=r0[5];
            accA[s][0]+=t0*a0+t1*a1+t2*a2; accA[s][1]+=t1*a0+t2*a1+t3*a2;
            accA[s][2]+=t2*a0+t3*a1+t4*a2; accA[s][3]+=t3*a0+t4*a1+t5*a2;
            accB[s][0]+=t0*b0+t1*b1+t2*b2; accB[s][1]+=t1*b0+t2*b1+t3*b2;
            accB[s][2]+=t2*b0+t3*b1+t4*b2; accB[s][3]+=t3*b0+t4*b1+t5*b2;
            t0=r1[0];t1=r1[1];t2=r1[2];t3=r1[3];t4=r1[4];t5=r1[5];
            accA[s][0]+=t0*a3+t1*a4+t2*a5; accA[s][1]+=t1*a3+t2*a4+t3*a5;
            accA[s][2]+=t2*a3+t3*a4+t4*a5; accA[s][3]+=t3*a3+t4*a4+t5*a5;
            accB[s][0]+=t0*b3+t1*b4+t2*b5; accB[s][1]+=t1*b3+t2*b4+t3*b5;
            accB[s][2]+=t2*b3+t3*b4+t4*b5; accB[s][3]+=t3*b3+t4*b4+t5*b5;
            t0=r2[0];t1=r2[1];t2=r2[2];t3=r2[3];t4=r2[4];t5=r2[5];
            accA[s][0]+=t0*a6+t1*a7+t2*a8; accA[s][1]+=t1*a6+t2*a7+t3*a8;
            accA[s][2]+=t2*a6+t3*a7+t4*a8; accA[s][3]+=t3*a6+t4*a7+t5*a8;
            accB[s][0]+=t0*b6+t1*b7+t2*b8; accB[s][1]+=t1*b6+t2*b7+t3*b8;
            accB[s][2]+=t2*b6+t3*b7+t4*b8; accB[s][3]+=t3*b6+t4*b7+t5*b8;
        }
    }
    float s1a=0.f, s2a=0.f, s1b=0.f, s2b=0.f;
    {
        const float cba = bvec[co0], cbb = bvec[co0+1];
        float4* ypA = reinterpret_cast<float4*>(g_y + (size_t)(b*CH + co0)*NPIX);
        float4* ypB = reinterpret_cast<float4*>(g_y + (size_t)(b*CH + co0 + 1)*NPIX);
#pragma unroll
        for (int s = 0; s < 4; s++) {
            float v0=accA[s][0]+cba, v1=accA[s][1]+cba, v2=accA[s][2]+cba, v3=accA[s][3]+cba;
            ypA[s*256 + tid] = make_float4(v0,v1,v2,v3);
            s1a += v0+v1+v2+v3; s2a += v0*v0+v1*v1+v2*v2+v3*v3;
            float u0=accB[s][0]+cbb, u1=accB[s][1]+cbb, u2=accB[s][2]+cbb, u3=accB[s][3]+cbb;
            ypB[s*256 + tid] = make_float4(u0,u1,u2,u3);
            s1b += u0+u1+u2+u3; s2b += u0*u0+u1*u1+u2*u2+u3*u3;
        }
    }
#pragma unroll
    for (int m = 16; m >= 1; m >>= 1) {
        s1a += __shfl_xor_sync(0xffffffffu, s1a, m);
        s2a += __shfl_xor_sync(0xffffffffu, s2a, m);
        s1b += __shfl_xor_sync(0xffffffffu, s1b, m);
        s2b += __shfl_xor_sync(0xffffffffu, s2b, m);
    }
    __syncthreads();
    if ((tid & 31) == 0) {
        int ww = tid>>5;
        xs[ww] = s1a; xs[8+ww] = s2a; xs[16+ww] = s1b; xs[24+ww] = s2b;
    }
    __syncthreads();
    if (tid == 0) {
        float r1a=0.f, r2a=0.f, r1b=0.f, r2b=0.f;
        for (int i = 0; i < 8; i++) { r1a+=xs[i]; r2a+=xs[8+i]; r1b+=xs[16+i]; r2b+=xs[24+i]; }
        atomicAdd(&g_stats[co0], r1a);      atomicAdd(&g_stats[CH+co0], r2a);
        atomicAdd(&g_stats[co0+1], r1b);    atomicAdd(&g_stats[CH+co0+1], r2b);
    }
}

// ------------- BN + PReLU; feat in-place; RN split-bf16 transposed out ------
__global__ void __launch_bounds__(256) k_bnt(const float* __restrict__ scale,
                                             const float* __restrict__ bias,
                                             const float* __restrict__ pa) {
    __shared__ float t[64][65];
    __shared__ float msc[64], mof[64];
    const int b = blockIdx.y, i0 = blockIdx.x*64, tid = threadIdx.x;
    const float a = pa[0];
    if (tid < 64) {
        const float inv = 1.0f / (float)(BATCH*NPIX);
        float m = g_stats[tid]*inv, v = g_stats[CH+tid]*inv - m*m;
        float r = rsqrtf(v + 1e-5f);
        msc[tid] = r*scale[tid]; mof[tid] = bias[tid] - m*r*scale[tid];
    }
    __syncthreads();
#pragma unroll
    for (int k = 0; k < 16; k++) {
        int idx = tid + k*256, c = idx>>6, ii = idx&63;
        size_t o = (size_t)(b*CH + c)*NPIX + i0 + ii;
        float v = g_y[o]*msc[c] + mof[c];
        v = (v >= 0.f) ? v : a*v;
        g_y[o] = v; t[c][ii] = v;
    }
    __syncthreads();
#pragma unroll
    for (int k = 0; k < 8; k++) {
        int idx = tid + k*256, ii = idx>>5, cp = idx&31;
        float v0 = t[2*cp][ii], v1 = t[2*cp+1][ii];
        uint32_t hp = pack_bf2(v0, v1);                       // RN hi
        float h0 = __uint_as_float(hp << 16);
        float h1 = __uint_as_float(hp & 0xffff0000u);
        size_t o = ((size_t)b*NPIX + i0 + ii)*32 + cp;
        g_fh[o] = hp;
        g_fl[o] = pack_bf2(v0 - h0, v1 - h1);                 // RN residual
    }
}

// -- group (128 thr) stages its OWN 32x64 hi+lo half (4 cp.async/thread) ----
__device__ __forceinline__ void stg_g(uint32_t base, const unsigned* fh,
                                      const unsigned* fl, int j0, int jhalf, int gt) {
#pragma unroll
    for (int k = 0; k < 4; k++) {
        int idx = gt + k*128;                   // 0..511
        int hilo = idx >> 8;                    // 0: hi, 1: lo
        int rr = jhalf*32 + ((idx >> 3) & 31);
        int q = idx & 7;
        uint32_t dst = base + (uint32_t)hilo*8192u + (uint32_t)(rr*128) +
                       (uint32_t)((q*16) ^ ((rr & 7)*16));
        const unsigned* src = (hilo ? fl : fh) + (size_t)(j0 + rr)*32 + q*4;
        asm volatile("cp.async.cg.shared.global [%0], [%1], 16;" :: "r"(dst), "l"(src));
    }
    asm volatile("cp.async.commit_group;" ::: "memory");
}

// ---- flash attention: 64-row tile, 256 thr, 2 SMSP-interleaved groups -----
__global__ void __launch_bounds__(256, 2) k_attn(const float* __restrict__ gp,
                                                 float* __restrict__ out) {
    __shared__ __align__(1024) char ks[32768];
    __shared__ float mex[2][64], lex[2][64];
    const uint32_t ksb = smem_u32(ks);
    const int tid = threadIdx.x, w = tid >> 5, lane = tid & 31;
    const int g = lane >> 2, lam = lane & 3;
    const int wg = w & 3, jhalf = w >> 2;        // SMSP-interleaved groups
    const int gt = wg*32 + lane;
    const int it = blockIdx.x, b = blockIdx.y;
    const int i0 = it * 64;
    const int row0 = i0 + wg*16 + g, row1 = row0 + 8;
    const float L2E = 1.4426950408889634f;

    const unsigned* fh = g_fh + (size_t)b*NPIX*32;
    const unsigned* fl = g_fl + (size_t)b*NPIX*32;

    uint32_t qh[4][4], ql[4][4];
#pragma unroll
    for (int kc = 0; kc < 4; kc++) {
        qh[kc][0] = fh[(size_t)row0*32 + lam + 8*kc];
        qh[kc][1] = fh[(size_t)row1*32 + lam + 8*kc];
        qh[kc][2] = fh[(size_t)row0*32 + lam + 4 + 8*kc];
        qh[kc][3] = fh[(size_t)row1*32 + lam + 4 + 8*kc];
        ql[kc][0] = fl[(size_t)row0*32 + lam + 8*kc];
        ql[kc][1] = fl[(size_t)row1*32 + lam + 8*kc];
        ql[kc][2] = fl[(size_t)row0*32 + lam + 4 + 8*kc];
        ql[kc][3] = fl[(size_t)row1*32 + lam + 4 + 8*kc];
    }

    float o[8][4];
#pragma unroll
    for (int n = 0; n < 8; n++) { o[n][0]=o[n][1]=o[n][2]=o[n][3]=0.f; }
    float m0 = -1e30f, m1 = -1e30f, l0 = 0.f, l1 = 0.f;

    stg_g(ksb, fh, fl, 0, jhalf, gt);

    for (int jt = 0; jt < 64; jt++) {
        if (jt < 63) {
            stg_g(ksb + (uint32_t)(((jt+1)&1)*16384), fh, fl, (jt+1)*64, jhalf, gt);
            asm volatile("cp.async.wait_group 1;" ::: "memory");
        } else {
            asm volatile("cp.async.wait_group 0;" ::: "memory");
        }
        GBAR(1 + jhalf);
        const uint32_t kb = ksb + (uint32_t)((jt&1)*16384);

        // ---- S = Q.K^T over this warp's 32-col j-half (hh + hl + lh)
        float s[4][4];
#pragma unroll
        for (int n = 0; n < 4; n++) { s[n][0]=s[n][1]=s[n][2]=s[n][3]=0.f; }
#pragma unroll
        for (int jn2 = 0; jn2 < 2; jn2++) {
            const int jadr = jhalf*32 + 16*jn2 + (lane & 7) + ((lane >> 4) & 1)*8;
#pragma unroll
            for (int kc = 0; kc < 4; kc++) {
                const int q = 2*kc + ((lane >> 3) & 1);
                uint32_t ah = kb + (uint32_t)(jadr*128) + (uint32_t)((q*16) ^ ((jadr & 7)*16));
                uint32_t bh[4], bl[4];
                ldsm4(bh, ah);
                ldsm4(bl, ah + 8192u);
                mma(s[2*jn2],   qh[kc], bh[0], bh[1]);
                mma(s[2*jn2],   qh[kc], bl[0], bl[1]);
                mma(s[2*jn2],   ql[kc], bh[0], bh[1]);
                mma(s[2*jn2+1], qh[kc], bh[2], bh[3]);
                mma(s[2*jn2+1], qh[kc], bl[2], bl[3]);
                mma(s[2*jn2+1], ql[kc], bh[2], bh[3]);
            }
        }

        // ---- online softmax over this j-half, score = -s
        float mt0 = -1e30f, mt1 = -1e30f;
#pragma unroll
        for (int n = 0; n < 4; n++) {
            mt0 = fmaxf(mt0, fmaxf(-s[n][0], -s[n][1]));
            mt1 = fmaxf(mt1, fmaxf(-s[n][2], -s[n][3]));
        }
        mt0 = fmaxf(mt0, __shfl_xor_sync(0xffffffffu, mt0, 1));
        mt0 = fmaxf(mt0, __shfl_xor_sync(0xffffffffu, mt0, 2));
        mt1 = fmaxf(mt1, __shfl_xor_sync(0xffffffffu, mt1, 1));
        mt1 = fmaxf(mt1, __shfl_xor_sync(0xffffffffu, mt1, 2));
        const float mn0 = fmaxf(m0, mt0), mn1 = fmaxf(m1, mt1);
        const float a0 = ex2((m0 - mn0)*L2E), a1 = ex2((m1 - mn1)*L2E);
        const float nm0 = -mn0*L2E, nm1 = -mn1*L2E;
        const bool resc = !__all_sync(0xffffffffu, (mn0 == m0) & (mn1 == m1));
        m0 = mn0; m1 = mn1;
        uint32_t ph[4][2], pl[4][2];
        float sum0 = 0.f, sum1 = 0.f;
#pragma unroll
        for (int n = 0; n < 4; n++) {
            float p00 = ex2(fmaf(s[n][0], -L2E, nm0));
            float p01 = ex2(fmaf(s[n][1], -L2E, nm0));
            float p10 = ex2(fmaf(s[n][2], -L2E, nm1));
            float p11 = ex2(fmaf(s[n][3], -L2E, nm1));
            sum0 += p00 + p01; sum1 += p10 + p11;
            uint32_t u00 = __float_as_uint(p00) & 0xffff0000u;
            uint32_t u01 = __float_as_uint(p01) & 0xffff0000u;
            uint32_t u10 = __float_as_uint(p10) & 0xffff0000u;
            uint32_t u11 = __float_as_uint(p11) & 0xffff0000u;
            ph[n][0] = u01 | (u00 >> 16);
            ph[n][1] = u11 | (u10 >> 16);
            pl[n][0] = pack_bf2(p00 - __uint_as_float(u00), p01 - __uint_as_float(u01));
            pl[n][1] = pack_bf2(p10 - __uint_as_float(u10), p11 - __uint_as_float(u11));
        }
        l0 = l0*a0 + sum0; l1 = l1*a1 + sum1;
        if (resc) {
#pragma unroll
            for (int n = 0; n < 8; n++) {
                o[n][0] *= a0; o[n][1] *= a0; o[n][2] *= a1; o[n][3] *= a1;
            }
        }

        // ---- O += P.V over this warp's 32 j-rows: PhVh + PlVh (V hi only)
        {
            const int jadr = jhalf*32 + lane;
#pragma unroll
            for (int cn = 0; cn < 8; cn++) {
                uint32_t ad = kb + (uint32_t)(jadr*128) + (uint32_t)((cn*16) ^ ((jadr & 7)*16));
                uint32_t vh[4];
                ldsm4t(vh, ad);
#pragma unroll
                for (int t = 0; t < 2; t++) {
                    uint32_t aH[4] = { ph[2*t][0], ph[2*t][1], ph[2*t+1][0], ph[2*t+1][1] };
                    uint32_t aL[4] = { pl[2*t][0], pl[2*t][1], pl[2*t+1][0], pl[2*t+1][1] };
                    mma(o[cn], aH, vh[2*t], vh[2*t+1]);
                    mma(o[cn], aL, vh[2*t], vh[2*t+1]);
                }
            }
        }
        GBAR(1 + jhalf);
    }

    // ---- combine the two j-halves within the CTA
    l0 += __shfl_xor_sync(0xffffffffu, l0, 1);
    l0 += __shfl_xor_sync(0xffffffffu, l0, 2);
    l1 += __shfl_xor_sync(0xffffffffu, l1, 1);
    l1 += __shfl_xor_sync(0xffffffffu, l1, 2);
    const int r0 = wg*16 + g, r1 = r0 + 8;
    if (lam == 0) {
        mex[jhalf][r0] = m0; lex[jhalf][r0] = l0;
        mex[jhalf][r1] = m1; lex[jhalf][r1] = l1;
    }
    __syncthreads();
    float mm0 = fmaxf(mex[0][r0], mex[1][r0]);
    float mm1 = fmaxf(mex[0][r1], mex[1][r1]);
    float Lt0 = lex[0][r0]*ex2((mex[0][r0]-mm0)*L2E) + lex[1][r0]*ex2((mex[1][r0]-mm0)*L2E);
    float Lt1 = lex[0][r1]*ex2((mex[0][r1]-mm1)*L2E) + lex[1][r1]*ex2((mex[1][r1]-mm1)*L2E);
    const float sc0 = ex2((m0 - mm0)*L2E) / Lt0;
    const float sc1 = ex2((m1 - mm1)*L2E) / Lt1;
    float* ob = reinterpret_cast<float*>(ks);
    __syncthreads();
    if (jhalf == 0) {
#pragma unroll
        for (int cn = 0; cn < 8; cn++) {
            const int c0 = 8*cn + 2*lam;
            ob[r0*65 + c0]     = o[cn][0]*sc0;
            ob[r0*65 + c0 + 1] = o[cn][1]*sc0;
            ob[r1*65 + c0]     = o[cn][2]*sc1;
            ob[r1*65 + c0 + 1] = o[cn][3]*sc1;
        }
    }
    __syncthreads();
    if (jhalf == 1) {
#pragma unroll
        for (int cn = 0; cn < 8; cn++) {
            const int c0 = 8*cn + 2*lam;
            ob[r0*65 + c0]     += o[cn][0]*sc0;
            ob[r0*65 + c0 + 1] += o[cn][1]*sc0;
            ob[r1*65 + c0]     += o[cn][2]*sc1;
            ob[r1*65 + c0 + 1] += o[cn][3]*sc1;
        }
    }
    __syncthreads();
    const float gam = gp[0];
#pragma unroll
    for (int k = 0; k < 16; k++) {
        int idx = tid + k*256;
        int c = idx >> 6, r = idx & 63;
        size_t oo = (size_t)(b*CH + c)*NPIX + i0 + r;
        out[oo] = gam*ob[r*65 + c] + g_y[oo];
    }
}

extern "C" void kernel_launch(void* const* d_in, const int* in_sizes, int n_in,
                              void* d_out, int out_size) {
    const float* x     = (const float*)d_in[0];
    const float* cw    = (const float*)d_in[1];
    const float* cb    = (const float*)d_in[2];
    const float* bns   = (const float*)d_in[3];
    const float* bnb   = (const float*)d_in[4];
    const float* pa    = (const float*)d_in[5];
    const float* gamma = (const float*)d_in[6];
    float* out = (float*)d_out;

    static bool done = false;
    if (!done) {
        cudaFuncSetAttribute(k_attn, cudaFuncAttributePreferredSharedMemoryCarveout, 100);
        done = true;
    }

    k_init_stats<<<1, 128>>>();
    k_conv<<<dim3(32, BATCH), 256>>>(x, cw, cb);
    k_bnt<<<dim3(64, BATCH), 256>>>(bns, bnb, pa);
    k_attn<<<dim3(64, BATCH), 256>>>(gamma, out);
}

// round 16
// speedup vs baseline: 1.3234x; 1.1219x over previous
#include <cuda_runtime.h>
#include <cuda_fp16.h>
#include <math.h>
#include <stdint.h>

#define BATCH 4
#define CH 64
#define NPIX 4096
#define NTOT (BATCH*CH*NPIX)

__device__ float g_y[NTOT];                // conv out -> normalized feat (B,C,N)
__device__ unsigned g_fh[BATCH*NPIX*32];   // hi f16x2 (B,N,32)  (RN)
__device__ unsigned g_fl[BATCH*NPIX*32];   // lo f16x2 (RN residual)
__device__ float g_stats[2*CH];

__device__ __forceinline__ uint32_t smem_u32(const void* p) {
    uint32_t a;
    asm("{ .reg .u64 t; cvta.to.shared.u64 t, %1; cvt.u32.u64 %0, t; }" : "=r"(a) : "l"(p));
    return a;
}
__device__ __forceinline__ void ldsm4(uint32_t* r, uint32_t a) {
    asm volatile("ldmatrix.sync.aligned.m8n8.x4.shared.b16 {%0,%1,%2,%3}, [%4];"
        : "=r"(r[0]), "=r"(r[1]), "=r"(r[2]), "=r"(r[3]) : "r"(a));
}
__device__ __forceinline__ void ldsm4t(uint32_t* r, uint32_t a) {
    asm volatile("ldmatrix.sync.aligned.m8n8.x4.trans.shared.b16 {%0,%1,%2,%3}, [%4];"
        : "=r"(r[0]), "=r"(r[1]), "=r"(r[2]), "=r"(r[3]) : "r"(a));
}
__device__ __forceinline__ void mma(float* d, const uint32_t* a, uint32_t b0, uint32_t b1) {
    asm volatile("mma.sync.aligned.m16n8k16.row.col.f32.f16.f16.f32 "
        "{%0,%1,%2,%3}, {%4,%5,%6,%7}, {%8,%9}, {%0,%1,%2,%3};"
        : "+f"(d[0]), "+f"(d[1]), "+f"(d[2]), "+f"(d[3])
        : "r"(a[0]), "r"(a[1]), "r"(a[2]), "r"(a[3]), "r"(b0), "r"(b1));
}
__device__ __forceinline__ uint32_t pack_h2(float lo, float hi) {
    uint32_t d;
    asm("cvt.rn.f16x2.f32 %0, %1, %2;" : "=r"(d) : "f"(hi), "f"(lo));
    return d;
}
__device__ __forceinline__ float ex2(float x) {
    float r;
    asm("ex2.approx.f32 %0, %1;" : "=f"(r) : "f"(x));
    return r;
}
#define GBAR(id) asm volatile("bar.sync %0, %1;" :: "r"(id), "r"(128) : "memory")

__global__ void k_init_stats() { int t = threadIdx.x; if (t < 2*CH) g_stats[t] = 0.0f; }

// -------- conv 3x3 + bias, 2 c_out per CTA (grid 128 = one wave) ----------
__global__ void __launch_bounds__(256) k_conv(const float* __restrict__ x,
                                              const float* __restrict__ w,
                                              const float* __restrict__ bvec) {
    __shared__ float xs[66*66];
    const int co0 = blockIdx.x*2, b = blockIdx.y, tid = threadIdx.x;
    for (int i = tid; i < 66*66; i += 256) xs[i] = 0.0f;
    float accA[4][4], accB[4][4];
#pragma unroll
    for (int s = 0; s < 4; s++)
#pragma unroll
        for (int e = 0; e < 4; e++) { accA[s][e]=0.f; accB[s][e]=0.f; }
    const float4* xb4 = reinterpret_cast<const float4*>(x + (size_t)b*CH*NPIX);
    for (int ci = 0; ci < CH; ci++) {
        __syncthreads();
#pragma unroll
        for (int k = 0; k < 4; k++) {
            int lin = tid + k*256;
            float4 v = xb4[ci*1024 + lin];
            float* dst = xs + ((lin>>4)+1)*66 + ((lin&15)<<2) + 1;
            dst[0]=v.x; dst[1]=v.y; dst[2]=v.z; dst[3]=v.w;
        }
        __syncthreads();
        const float* wA = w + (co0*CH + ci)*9;
        const float* wB = w + ((co0+1)*CH + ci)*9;
        float a0=wA[0],a1=wA[1],a2=wA[2],a3=wA[3],a4=wA[4],a5=wA[5],a6=wA[6],a7=wA[7],a8=wA[8];
        float b0=wB[0],b1=wB[1],b2=wB[2],b3=wB[3],b4=wB[4],b5=wB[5],b6=wB[6],b7=wB[7],b8=wB[8];
#pragma unroll
        for (int s = 0; s < 4; s++) {
            int pb = s*1024 + tid*4;
            const float* r0 = xs + (pb>>6)*66 + (pb&63);
            const float* r1 = r0 + 66; const float* r2 = r1 + 66;
            float t0,t1,t2,t3,t4,t5;
            t0=r0[0];t1=r0[1];t2=r0[2];t3=r0[3];t4=r0[4];t5=r0[5];
            accA[s][0]+=t0*a0+t1*a1+t2*a2; accA[s][1]+=t1*a0+t2*a1+t3*a2;
            accA[s][2]+=t2*a0+t3*a1+t4*a2; accA[s][3]+=t3*a0+t4*a1+t5*a2;
            accB[s][0]+=t0*b0+t1*b1+t2*b2; accB[s][1]+=t1*b0+t2*b1+t3*b2;
            accB[s][2]+=t2*b0+t3*b1+t4*b2; accB[s][3]+=t3*b0+t4*b1+t5*b2;
            t0=r1[0];t1=r1[1];t2=r1[2];t3=r1[3];t4=r1[4];t5=r1[5];
            accA[s][0]+=t0*a3+t1*a4+t2*a5; accA[s][1]+=t1*a3+t2*a4+t3*a5;
            accA[s][2]+=t2*a3+t3*a4+t4*a5; accA[s][3]+=t3*a3+t4*a4+t5*a5;
            accB[s][0]+=t0*b3+t1*b4+t2*b5; accB[s][1]+=t1*b3+t2*b4+t3*b5;
            accB[s][2]+=t2*b3+t3*b4+t4*b5; accB[s][3]+=t3*b3+t4*b4+t5*b5;
            t0=r2[0];t1=r2[1];t2=r2[2];t3=r2[3];t4=r2[4];t5=r2[5];
            accA[s][0]+=t0*a6+t1*a7+t2*a8; accA[s][1]+=t1*a6+t2*a7+t3*a8;
            accA[s][2]+=t2*a6+t3*a7+t4*a8; accA[s][3]+=t3*a6+t4*a7+t5*a8;
            accB[s][0]+=t0*b6+t1*b7+t2*b8; accB[s][1]+=t1*b6+t2*b7+t3*b8;
            accB[s][2]+=t2*b6+t3*b7+t4*b8; accB[s][3]+=t3*b6+t4*b7+t5*b8;
        }
    }
    float s1a=0.f, s2a=0.f, s1b=0.f, s2b=0.f;
    {
        const float cba = bvec[co0], cbb = bvec[co0+1];
        float4* ypA = reinterpret_cast<float4*>(g_y + (size_t)(b*CH + co0)*NPIX);
        float4* ypB = reinterpret_cast<float4*>(g_y + (size_t)(b*CH + co0 + 1)*NPIX);
#pragma unroll
        for (int s = 0; s < 4; s++) {
            float v0=accA[s][0]+cba, v1=accA[s][1]+cba, v2=accA[s][2]+cba, v3=accA[s][3]+cba;
            ypA[s*256 + tid] = make_float4(v0,v1,v2,v3);
            s1a += v0+v1+v2+v3; s2a += v0*v0+v1*v1+v2*v2+v3*v3;
            float u0=accB[s][0]+cbb, u1=accB[s][1]+cbb, u2=accB[s][2]+cbb, u3=accB[s][3]+cbb;
            ypB[s*256 + tid] = make_float4(u0,u1,u2,u3);
            s1b += u0+u1+u2+u3; s2b += u0*u0+u1*u1+u2*u2+u3*u3;
        }
    }
#pragma unroll
    for (int m = 16; m >= 1; m >>= 1) {
        s1a += __shfl_xor_sync(0xffffffffu, s1a, m);
        s2a += __shfl_xor_sync(0xffffffffu, s2a, m);
        s1b += __shfl_xor_sync(0xffffffffu, s1b, m);
        s2b += __shfl_xor_sync(0xffffffffu, s2b, m);
    }
    __syncthreads();
    if ((tid & 31) == 0) {
        int ww = tid>>5;
        xs[ww] = s1a; xs[8+ww] = s2a; xs[16+ww] = s1b; xs[24+ww] = s2b;
    }
    __syncthreads();
    if (tid == 0) {
        float r1a=0.f, r2a=0.f, r1b=0.f, r2b=0.f;
        for (int i = 0; i < 8; i++) { r1a+=xs[i]; r2a+=xs[8+i]; r1b+=xs[16+i]; r2b+=xs[24+i]; }
        atomicAdd(&g_stats[co0], r1a);      atomicAdd(&g_stats[CH+co0], r2a);
        atomicAdd(&g_stats[co0+1], r1b);    atomicAdd(&g_stats[CH+co0+1], r2b);
    }
}

// ------------- BN + PReLU; feat in-place; RN split-fp16 transposed out ------
__global__ void __launch_bounds__(256) k_bnt(const float* __restrict__ scale,
                                             const float* __restrict__ bias,
                                             const float* __restrict__ pa) {
    __shared__ float t[64][65];
    __shared__ float msc[64], mof[64];
    const int b = blockIdx.y, i0 = blockIdx.x*64, tid = threadIdx.x;
    const float a = pa[0];
    if (tid < 64) {
        const float inv = 1.0f / (float)(BATCH*NPIX);
        float m = g_stats[tid]*inv, v = g_stats[CH+tid]*inv - m*m;
        float r = rsqrtf(v + 1e-5f);
        msc[tid] = r*scale[tid]; mof[tid] = bias[tid] - m*r*scale[tid];
    }
    __syncthreads();
#pragma unroll
    for (int k = 0; k < 16; k++) {
        int idx = tid + k*256, c = idx>>6, ii = idx&63;
        size_t o = (size_t)(b*CH + c)*NPIX + i0 + ii;
        float v = g_y[o]*msc[c] + mof[c];
        v = (v >= 0.f) ? v : a*v;
        g_y[o] = v; t[c][ii] = v;
    }
    __syncthreads();
#pragma unroll
    for (int k = 0; k < 8; k++) {
        int idx = tid + k*256, ii = idx>>5, cp = idx&31;
        float v0 = t[2*cp][ii], v1 = t[2*cp+1][ii];
        uint32_t hp = pack_h2(v0, v1);                        // RN fp16 hi (lo=v0, hi=v1)
        __half2 hh = *reinterpret_cast<__half2*>(&hp);
        float2 hf = __half22float2(hh);
        size_t o = ((size_t)b*NPIX + i0 + ii)*32 + cp;
        g_fh[o] = hp;
        g_fl[o] = pack_h2(v0 - hf.x, v1 - hf.y);              // RN fp16 residual
    }
}

// -- group (128 thr) stages its OWN 32x64 hi+lo half (4 cp.async/thread) ----
__device__ __forceinline__ void stg_g(uint32_t base, const unsigned* fh,
                                      const unsigned* fl, int j0, int jhalf, int gt) {
#pragma unroll
    for (int k = 0; k < 4; k++) {
        int idx = gt + k*128;                   // 0..511
        int hilo = idx >> 8;                    // 0: hi, 1: lo
        int rr = jhalf*32 + ((idx >> 3) & 31);
        int q = idx & 7;
        uint32_t dst = base + (uint32_t)hilo*8192u + (uint32_t)(rr*128) +
                       (uint32_t)((q*16) ^ ((rr & 7)*16));
        const unsigned* src = (hilo ? fl : fh) + (size_t)(j0 + rr)*32 + q*4;
        asm volatile("cp.async.cg.shared.global [%0], [%1], 16;" :: "r"(dst), "l"(src));
    }
    asm volatile("cp.async.commit_group;" ::: "memory");
}

// ---- flash attention: 64-row tile, 256 thr, 2 SMSP-interleaved groups -----
// fp16 split: S = QhKh + QhKl + QlKh (fp32 acc); O = PhVh only.
__global__ void __launch_bounds__(256, 2) k_attn(const float* __restrict__ gp,
                                                 float* __restrict__ out) {
    __shared__ __align__(1024) char ks[32768];
    __shared__ float mex[2][64], lex[2][64];
    const uint32_t ksb = smem_u32(ks);
    const int tid = threadIdx.x, w = tid >> 5, lane = tid & 31;
    const int g = lane >> 2, lam = lane & 3;
    const int wg = w & 3, jhalf = w >> 2;        // SMSP-interleaved groups
    const int gt = wg*32 + lane;
    const int it = blockIdx.x, b = blockIdx.y;
    const int i0 = it * 64;
    const int row0 = i0 + wg*16 + g, row1 = row0 + 8;
    const float L2E = 1.4426950408889634f;

    const unsigned* fh = g_fh + (size_t)b*NPIX*32;
    const unsigned* fl = g_fl + (size_t)b*NPIX*32;

    uint32_t qh[4][4], ql[4][4];
#pragma unroll
    for (int kc = 0; kc < 4; kc++) {
        qh[kc][0] = fh[(size_t)row0*32 + lam + 8*kc];
        qh[kc][1] = fh[(size_t)row1*32 + lam + 8*kc];
        qh[kc][2] = fh[(size_t)row0*32 + lam + 4 + 8*kc];
        qh[kc][3] = fh[(size_t)row1*32 + lam + 4 + 8*kc];
        ql[kc][0] = fl[(size_t)row0*32 + lam + 8*kc];
        ql[kc][1] = fl[(size_t)row1*32 + lam + 8*kc];
        ql[kc][2] = fl[(size_t)row0*32 + lam + 4 + 8*kc];
        ql[kc][3] = fl[(size_t)row1*32 + lam + 4 + 8*kc];
    }

    float o[8][4];
#pragma unroll
    for (int n = 0; n < 8; n++) { o[n][0]=o[n][1]=o[n][2]=o[n][3]=0.f; }
    float m0 = -1e30f, m1 = -1e30f, l0 = 0.f, l1 = 0.f;

    stg_g(ksb, fh, fl, 0, jhalf, gt);

    for (int jt = 0; jt < 64; jt++) {
        if (jt < 63) {
            stg_g(ksb + (uint32_t)(((jt+1)&1)*16384), fh, fl, (jt+1)*64, jhalf, gt);
            asm volatile("cp.async.wait_group 1;" ::: "memory");
        } else {
            asm volatile("cp.async.wait_group 0;" ::: "memory");
        }
        GBAR(1 + jhalf);
        const uint32_t kb = ksb + (uint32_t)((jt&1)*16384);

        // ---- S = Q.K^T over this warp's 32-col j-half (hh + hl + lh)
        float s[4][4];
#pragma unroll
        for (int n = 0; n < 4; n++) { s[n][0]=s[n][1]=s[n][2]=s[n][3]=0.f; }
#pragma unroll
        for (int jn2 = 0; jn2 < 2; jn2++) {
            const int jadr = jhalf*32 + 16*jn2 + (lane & 7) + ((lane >> 4) & 1)*8;
#pragma unroll
            for (int kc = 0; kc < 4; kc++) {
                const int q = 2*kc + ((lane >> 3) & 1);
                uint32_t ah = kb + (uint32_t)(jadr*128) + (uint32_t)((q*16) ^ ((jadr & 7)*16));
                uint32_t bh[4], bl[4];
                ldsm4(bh, ah);
                ldsm4(bl, ah + 8192u);
                mma(s[2*jn2],   qh[kc], bh[0], bh[1]);
                mma(s[2*jn2],   qh[kc], bl[0], bl[1]);
                mma(s[2*jn2],   ql[kc], bh[0], bh[1]);
                mma(s[2*jn2+1], qh[kc], bh[2], bh[3]);
                mma(s[2*jn2+1], qh[kc], bl[2], bl[3]);
                mma(s[2*jn2+1], ql[kc], bh[2], bh[3]);
            }
        }

        // ---- online softmax over this j-half, score = -s
        float mt0 = -1e30f, mt1 = -1e30f;
#pragma unroll
        for (int n = 0; n < 4; n++) {
            mt0 = fmaxf(mt0, fmaxf(-s[n][0], -s[n][1]));
            mt1 = fmaxf(mt1, fmaxf(-s[n][2], -s[n][3]));
        }
        mt0 = fmaxf(mt0, __shfl_xor_sync(0xffffffffu, mt0, 1));
        mt0 = fmaxf(mt0, __shfl_xor_sync(0xffffffffu, mt0, 2));
        mt1 = fmaxf(mt1, __shfl_xor_sync(0xffffffffu, mt1, 1));
        mt1 = fmaxf(mt1, __shfl_xor_sync(0xffffffffu, mt1, 2));
        const float mn0 = fmaxf(m0, mt0), mn1 = fmaxf(m1, mt1);
        const float a0 = ex2((m0 - mn0)*L2E), a1 = ex2((m1 - mn1)*L2E);
        const float nm0 = -mn0*L2E, nm1 = -mn1*L2E;
        const bool resc = !__all_sync(0xffffffffu, (mn0 == m0) & (mn1 == m1));
        m0 = mn0; m1 = mn1;
        uint32_t ph[4][2];
        float sum0 = 0.f, sum1 = 0.f;
#pragma unroll
        for (int n = 0; n < 4; n++) {
            float p00 = ex2(fmaf(s[n][0], -L2E, nm0));
            float p01 = ex2(fmaf(s[n][1], -L2E, nm0));
            float p10 = ex2(fmaf(s[n][2], -L2E, nm1));
            float p11 = ex2(fmaf(s[n][3], -L2E, nm1));
            sum0 += p00 + p01; sum1 += p10 + p11;
            ph[n][0] = pack_h2(p00, p01);
            ph[n][1] = pack_h2(p10, p11);
        }
        l0 = l0*a0 + sum0; l1 = l1*a1 + sum1;
        if (resc) {
#pragma unroll
            for (int n = 0; n < 8; n++) {
                o[n][0] *= a0; o[n][1] *= a0; o[n][2] *= a1; o[n][3] *= a1;
            }
        }

        // ---- O += Ph.Vh over this warp's 32 j-rows (single term)
        {
            const int jadr = jhalf*32 + lane;
#pragma unroll
            for (int cn = 0; cn < 8; cn++) {
                uint32_t ad = kb + (uint32_t)(jadr*128) + (uint32_t)((cn*16) ^ ((jadr & 7)*16));
                uint32_t vh[4];
                ldsm4t(vh, ad);
#pragma unroll
                for (int t = 0; t < 2; t++) {
                    uint32_t aH[4] = { ph[2*t][0], ph[2*t][1], ph[2*t+1][0], ph[2*t+1][1] };
                    mma(o[cn], aH, vh[2*t], vh[2*t+1]);
                }
            }
        }
        GBAR(1 + jhalf);
    }

    // ---- combine the two j-halves within the CTA
    l0 += __shfl_xor_sync(0xffffffffu, l0, 1);
    l0 += __shfl_xor_sync(0xffffffffu, l0, 2);
    l1 += __shfl_xor_sync(0xffffffffu, l1, 1);
    l1 += __shfl_xor_sync(0xffffffffu, l1, 2);
    const int r0 = wg*16 + g, r1 = r0 + 8;
    if (lam == 0) {
        mex[jhalf][r0] = m0; lex[jhalf][r0] = l0;
        mex[jhalf][r1] = m1; lex[jhalf][r1] = l1;
    }
    __syncthreads();
    float mm0 = fmaxf(mex[0][r0], mex[1][r0]);
    float mm1 = fmaxf(mex[0][r1], mex[1][r1]);
    float Lt0 = lex[0][r0]*ex2((mex[0][r0]-mm0)*L2E) + lex[1][r0]*ex2((mex[1][r0]-mm0)*L2E);
    float Lt1 = lex[0][r1]*ex2((mex[0][r1]-mm1)*L2E) + lex[1][r1]*ex2((mex[1][r1]-mm1)*L2E);
    const float sc0 = ex2((m0 - mm0)*L2E) / Lt0;
    const float sc1 = ex2((m1 - mm1)*L2E) / Lt1;
    float* ob = reinterpret_cast<float*>(ks);
    __syncthreads();
    if (jhalf == 0) {
#pragma unroll
        for (int cn = 0; cn < 8; cn++) {
            const int c0 = 8*cn + 2*lam;
            ob[r0*65 + c0]     = o[cn][0]*sc0;
            ob[r0*65 + c0 + 1] = o[cn][1]*sc0;
            ob[r1*65 + c0]     = o[cn][2]*sc1;
            ob[r1*65 + c0 + 1] = o[cn][3]*sc1;
        }
    }
    __syncthreads();
    if (jhalf == 1) {
#pragma unroll
        for (int cn = 0; cn < 8; cn++) {
            const int c0 = 8*cn + 2*lam;
            ob[r0*65 + c0]     += o[cn][0]*sc0;
            ob[r0*65 + c0 + 1] += o[cn][1]*sc0;
            ob[r1*65 + c0]     += o[cn][2]*sc1;
            ob[r1*65 + c0 + 1] += o[cn][3]*sc1;
        }
    }
    __syncthreads();
    const float gam = gp[0];
#pragma unroll
    for (int k = 0; k < 16; k++) {
        int idx = tid + k*256;
        int c = idx >> 6, r = idx & 63;
        size_t oo = (size_t)(b*CH + c)*NPIX + i0 + r;
        out[oo] = gam*ob[r*65 + c] + g_y[oo];
    }
}

extern "C" void kernel_launch(void* const* d_in, const int* in_sizes, int n_in,
                              void* d_out, int out_size) {
    const float* x     = (const float*)d_in[0];
    const float* cw    = (const float*)d_in[1];
    const float* cb    = (const float*)d_in[2];
    const float* bns   = (const float*)d_in[3];
    const float* bnb   = (const float*)d_in[4];
    const float* pa    = (const float*)d_in[5];
    const float* gamma = (const float*)d_in[6];
    float* out = (float*)d_out;

    static bool done = false;
    if (!done) {
        cudaFuncSetAttribute(k_attn, cudaFuncAttributePreferredSharedMemoryCarveout, 100);
        done = true;
    }

    k_init_stats<<<1, 128>>>();
    k_conv<<<dim3(32, BATCH), 256>>>(x, cw, cb);
    k_bnt<<<dim3(64, BATCH), 256>>>(bns, bnb, pa);
    k_attn<<<dim3(64, BATCH), 256>>>(gamma, out);
}

// round 17
// speedup vs baseline: 1.4686x; 1.1097x over previous
#include <cuda_runtime.h>
#include <cuda_fp16.h>
#include <math.h>
#include <stdint.h>

#define BATCH 4
#define CH 64
#define NPIX 4096
#define NTOT (BATCH*CH*NPIX)

__device__ float g_y[NTOT];                // conv out -> normalized feat (B,C,N)
__device__ unsigned g_fh[BATCH*NPIX*32];   // hi f16x2 (B,N,32)  (RN)
__device__ unsigned g_fl[BATCH*NPIX*32];   // lo f16x2 (RN residual)
__device__ float g_stats[2*CH];

__device__ __forceinline__ uint32_t smem_u32(const void* p) {
    uint32_t a;
    asm("{ .reg .u64 t; cvta.to.shared.u64 t, %1; cvt.u32.u64 %0, t; }" : "=r"(a) : "l"(p));
    return a;
}
__device__ __forceinline__ void ldsm4(uint32_t* r, uint32_t a) {
    asm volatile("ldmatrix.sync.aligned.m8n8.x4.shared.b16 {%0,%1,%2,%3}, [%4];"
        : "=r"(r[0]), "=r"(r[1]), "=r"(r[2]), "=r"(r[3]) : "r"(a));
}
__device__ __forceinline__ void ldsm4t(uint32_t* r, uint32_t a) {
    asm volatile("ldmatrix.sync.aligned.m8n8.x4.trans.shared.b16 {%0,%1,%2,%3}, [%4];"
        : "=r"(r[0]), "=r"(r[1]), "=r"(r[2]), "=r"(r[3]) : "r"(a));
}
__device__ __forceinline__ void mma(float* d, const uint32_t* a, uint32_t b0, uint32_t b1) {
    asm volatile("mma.sync.aligned.m16n8k16.row.col.f32.f16.f16.f32 "
        "{%0,%1,%2,%3}, {%4,%5,%6,%7}, {%8,%9}, {%0,%1,%2,%3};"
        : "+f"(d[0]), "+f"(d[1]), "+f"(d[2]), "+f"(d[3])
        : "r"(a[0]), "r"(a[1]), "r"(a[2]), "r"(a[3]), "r"(b0), "r"(b1));
}
__device__ __forceinline__ uint32_t pack_h2(float lo, float hi) {
    uint32_t d;
    asm("cvt.rn.f16x2.f32 %0, %1, %2;" : "=r"(d) : "f"(hi), "f"(lo));
    return d;
}
__device__ __forceinline__ float ex2(float x) {
    float r;
    asm("ex2.approx.f32 %0, %1;" : "=f"(r) : "f"(x));
    return r;
}
#define GBAR(id) asm volatile("bar.sync %0, %1;" :: "r"(id), "r"(128) : "memory")

__global__ void k_init_stats() { int t = threadIdx.x; if (t < 2*CH) g_stats[t] = 0.0f; }

// -------- conv 3x3 + bias, 2 c_out per CTA (grid 128 = one wave) ----------
__global__ void __launch_bounds__(256) k_conv(const float* __restrict__ x,
                                              const float* __restrict__ w,
                                              const float* __restrict__ bvec) {
    __shared__ float xs[66*66];
    const int co0 = blockIdx.x*2, b = blockIdx.y, tid = threadIdx.x;
    for (int i = tid; i < 66*66; i += 256) xs[i] = 0.0f;
    float accA[4][4], accB[4][4];
#pragma unroll
    for (int s = 0; s < 4; s++)
#pragma unroll
        for (int e = 0; e < 4; e++) { accA[s][e]=0.f; accB[s][e]=0.f; }
    const float4* xb4 = reinterpret_cast<const float4*>(x + (size_t)b*CH*NPIX);
    for (int ci = 0; ci < CH; ci++) {
        __syncthreads();
#pragma unroll
        for (int k = 0; k < 4; k++) {
            int lin = tid + k*256;
            float4 v = xb4[ci*1024 + lin];
            float* dst = xs + ((lin>>4)+1)*66 + ((lin&15)<<2) + 1;
            dst[0]=v.x; dst[1]=v.y; dst[2]=v.z; dst[3]=v.w;
        }
        __syncthreads();
        const float* wA = w + (co0*CH + ci)*9;
        const float* wB = w + ((co0+1)*CH + ci)*9;
        float a0=wA[0],a1=wA[1],a2=wA[2],a3=wA[3],a4=wA[4],a5=wA[5],a6=wA[6],a7=wA[7],a8=wA[8];
        float b0=wB[0],b1=wB[1],b2=wB[2],b3=wB[3],b4=wB[4],b5=wB[5],b6=wB[6],b7=wB[7],b8=wB[8];
#pragma unroll
        for (int s = 0; s < 4; s++) {
            int pb = s*1024 + tid*4;
            const float* r0 = xs + (pb>>6)*66 + (pb&63);
            const float* r1 = r0 + 66; const float* r2 = r1 + 66;
            float t0,t1,t2,t3,t4,t5;
            t0=r0[0];t1=r0[1];t2=r0[2];t3=r0[3];t4=r0[4];t5=r0[5];
            accA[s][0]+=t0*a0+t1*a1+t2*a2; accA[s][1]+=t1*a0+t2*a1+t3*a2;
            accA[s][2]+=t2*a0+t3*a1+t4*a2; accA[s][3]+=t3*a0+t4*a1+t5*a2;
            accB[s][0]+=t0*b0+t1*b1+t2*b2; accB[s][1]+=t1*b0+t2*b1+t3*b2;
            accB[s][2]+=t2*b0+t3*b1+t4*b2; accB[s][3]+=t3*b0+t4*b1+t5*b2;
            t0=r1[0];t1=r1[1];t2=r1[2];t3=r1[3];t4=r1[4];t5=r1[5];
            accA[s][0]+=t0*a3+t1*a4+t2*a5; accA[s][1]+=t1*a3+t2*a4+t3*a5;
            accA[s][2]+=t2*a3+t3*a4+t4*a5; accA[s][3]+=t3*a3+t4*a4+t5*a5;
            accB[s][0]+=t0*b3+t1*b4+t2*b5; accB[s][1]+=t1*b3+t2*b4+t3*b5;
            accB[s][2]+=t2*b3+t3*b4+t4*b5; accB[s][3]+=t3*b3+t4*b4+t5*b5;
            t0=r2[0];t1=r2[1];t2=r2[2];t3=r2[3];t4=r2[4];t5=r2[5];
            accA[s][0]+=t0*a6+t1*a7+t2*a8; accA[s][1]+=t1*a6+t2*a7+t3*a8;
            accA[s][2]+=t2*a6+t3*a7+t4*a8; accA[s][3]+=t3*a6+t4*a7+t5*a8;
            accB[s][0]+=t0*b6+t1*b7+t2*b8; accB[s][1]+=t1*b6+t2*b7+t3*b8;
            accB[s][2]+=t2*b6+t3*b7+t4*b8; accB[s][3]+=t3*b6+t4*b7+t5*b8;
        }
    }
    float s1a=0.f, s2a=0.f, s1b=0.f, s2b=0.f;
    {
        const float cba = bvec[co0], cbb = bvec[co0+1];
        float4* ypA = reinterpret_cast<float4*>(g_y + (size_t)(b*CH + co0)*NPIX);
        float4* ypB = reinterpret_cast<float4*>(g_y + (size_t)(b*CH + co0 + 1)*NPIX);
#pragma unroll
        for (int s = 0; s < 4; s++) {
            float v0=accA[s][0]+cba, v1=accA[s][1]+cba, v2=accA[s][2]+cba, v3=accA[s][3]+cba;
            ypA[s*256 + tid] = make_float4(v0,v1,v2,v3);
            s1a += v0+v1+v2+v3; s2a += v0*v0+v1*v1+v2*v2+v3*v3;
            float u0=accB[s][0]+cbb, u1=accB[s][1]+cbb, u2=accB[s][2]+cbb, u3=accB[s][3]+cbb;
            ypB[s*256 + tid] = make_float4(u0,u1,u2,u3);
            s1b += u0+u1+u2+u3; s2b += u0*u0+u1*u1+u2*u2+u3*u3;
        }
    }
#pragma unroll
    for (int m = 16; m >= 1; m >>= 1) {
        s1a += __shfl_xor_sync(0xffffffffu, s1a, m);
        s2a += __shfl_xor_sync(0xffffffffu, s2a, m);
        s1b += __shfl_xor_sync(0xffffffffu, s1b, m);
        s2b += __shfl_xor_sync(0xffffffffu, s2b, m);
    }
    __syncthreads();
    if ((tid & 31) == 0) {
        int ww = tid>>5;
        xs[ww] = s1a; xs[8+ww] = s2a; xs[16+ww] = s1b; xs[24+ww] = s2b;
    }
    __syncthreads();
    if (tid == 0) {
        float r1a=0.f, r2a=0.f, r1b=0.f, r2b=0.f;
        for (int i = 0; i < 8; i++) { r1a+=xs[i]; r2a+=xs[8+i]; r1b+=xs[16+i]; r2b+=xs[24+i]; }
        atomicAdd(&g_stats[co0], r1a);      atomicAdd(&g_stats[CH+co0], r2a);
        atomicAdd(&g_stats[co0+1], r1b);    atomicAdd(&g_stats[CH+co0+1], r2b);
    }
}

// ------------- BN + PReLU; feat in-place; RN split-fp16 transposed out ------
__global__ void __launch_bounds__(256) k_bnt(const float* __restrict__ scale,
                                             const float* __restrict__ bias,
                                             const float* __restrict__ pa) {
    __shared__ float t[64][65];
    __shared__ float msc[64], mof[64];
    const int b = blockIdx.y, i0 = blockIdx.x*64, tid = threadIdx.x;
    const float a = pa[0];
    if (tid < 64) {
        const float inv = 1.0f / (float)(BATCH*NPIX);
        float m = g_stats[tid]*inv, v = g_stats[CH+tid]*inv - m*m;
        float r = rsqrtf(v + 1e-5f);
        msc[tid] = r*scale[tid]; mof[tid] = bias[tid] - m*r*scale[tid];
    }
    __syncthreads();
#pragma unroll
    for (int k = 0; k < 16; k++) {
        int idx = tid + k*256, c = idx>>6, ii = idx&63;
        size_t o = (size_t)(b*CH + c)*NPIX + i0 + ii;
        float v = g_y[o]*msc[c] + mof[c];
        v = (v >= 0.f) ? v : a*v;
        g_y[o] = v; t[c][ii] = v;
    }
    __syncthreads();
#pragma unroll
    for (int k = 0; k < 8; k++) {
        int idx = tid + k*256, ii = idx>>5, cp = idx&31;
        float v0 = t[2*cp][ii], v1 = t[2*cp+1][ii];
        uint32_t hp = pack_h2(v0, v1);                        // RN fp16 hi
        __half2 hh = *reinterpret_cast<__half2*>(&hp);
        float2 hf = __half22float2(hh);
        size_t o = ((size_t)b*NPIX + i0 + ii)*32 + cp;
        g_fh[o] = hp;
        g_fl[o] = pack_h2(v0 - hf.x, v1 - hf.y);              // RN fp16 residual
    }
}

// -- group (128 thr) stages its OWN 32x64 hi+lo half (4 cp.async/thread) ----
__device__ __forceinline__ void stg_g(uint32_t base, const unsigned* fh,
                                      const unsigned* fl, int j0, int jhalf, int gt) {
#pragma unroll
    for (int k = 0; k < 4; k++) {
        int idx = gt + k*128;                   // 0..511
        int hilo = idx >> 8;                    // 0: hi, 1: lo
        int rr = jhalf*32 + ((idx >> 3) & 31);
        int q = idx & 7;
        uint32_t dst = base + (uint32_t)hilo*8192u + (uint32_t)(rr*128) +
                       (uint32_t)((q*16) ^ ((rr & 7)*16));
        const unsigned* src = (hilo ? fl : fh) + (size_t)(j0 + rr)*32 + q*4;
        asm volatile("cp.async.cg.shared.global [%0], [%1], 16;" :: "r"(dst), "l"(src));
    }
    asm volatile("cp.async.commit_group;" ::: "memory");
}

// ---- flash attention: 64-row tile, 256 thr, 2 SMSP-interleaved groups -----
// fp16 split: S = QhKh + QhKl (fp32 acc); O = PhVh.
__global__ void __launch_bounds__(256, 2) k_attn(const float* __restrict__ gp,
                                                 float* __restrict__ out) {
    __shared__ __align__(1024) char ks[32768];
    __shared__ float mex[2][64], lex[2][64];
    const uint32_t ksb = smem_u32(ks);
    const int tid = threadIdx.x, w = tid >> 5, lane = tid & 31;
    const int g = lane >> 2, lam = lane & 3;
    const int wg = w & 3, jhalf = w >> 2;        // SMSP-interleaved groups
    const int gt = wg*32 + lane;
    const int it = blockIdx.x, b = blockIdx.y;
    const int i0 = it * 64;
    const int row0 = i0 + wg*16 + g, row1 = row0 + 8;
    const float L2E = 1.4426950408889634f;

    const unsigned* fh = g_fh + (size_t)b*NPIX*32;
    const unsigned* fl = g_fl + (size_t)b*NPIX*32;

    uint32_t qh[4][4];
#pragma unroll
    for (int kc = 0; kc < 4; kc++) {
        qh[kc][0] = fh[(size_t)row0*32 + lam + 8*kc];
        qh[kc][1] = fh[(size_t)row1*32 + lam + 8*kc];
        qh[kc][2] = fh[(size_t)row0*32 + lam + 4 + 8*kc];
        qh[kc][3] = fh[(size_t)row1*32 + lam + 4 + 8*kc];
    }

    float o[8][4];
#pragma unroll
    for (int n = 0; n < 8; n++) { o[n][0]=o[n][1]=o[n][2]=o[n][3]=0.f; }
    float m0 = -1e30f, m1 = -1e30f, l0 = 0.f, l1 = 0.f;

    stg_g(ksb, fh, fl, 0, jhalf, gt);

    for (int jt = 0; jt < 64; jt++) {
        if (jt < 63) {
            stg_g(ksb + (uint32_t)(((jt+1)&1)*16384), fh, fl, (jt+1)*64, jhalf, gt);
            asm volatile("cp.async.wait_group 1;" ::: "memory");
        } else {
            asm volatile("cp.async.wait_group 0;" ::: "memory");
        }
        GBAR(1 + jhalf);
        const uint32_t kb = ksb + (uint32_t)((jt&1)*16384);

        // ---- S = Qh.Kh + Qh.Kl over this warp's 32-col j-half
        float s[4][4];
#pragma unroll
        for (int n = 0; n < 4; n++) { s[n][0]=s[n][1]=s[n][2]=s[n][3]=0.f; }
#pragma unroll
        for (int jn2 = 0; jn2 < 2; jn2++) {
            const int jadr = jhalf*32 + 16*jn2 + (lane & 7) + ((lane >> 4) & 1)*8;
#pragma unroll
            for (int kc = 0; kc < 4; kc++) {
                const int q = 2*kc + ((lane >> 3) & 1);
                uint32_t ah = kb + (uint32_t)(jadr*128) + (uint32_t)((q*16) ^ ((jadr & 7)*16));
                uint32_t bh[4], bl[4];
                ldsm4(bh, ah);
                ldsm4(bl, ah + 8192u);
                mma(s[2*jn2],   qh[kc], bh[0], bh[1]);
                mma(s[2*jn2],   qh[kc], bl[0], bl[1]);
                mma(s[2*jn2+1], qh[kc], bh[2], bh[3]);
                mma(s[2*jn2+1], qh[kc], bl[2], bl[3]);
            }
        }

        // ---- online softmax over this j-half, score = -s
        float mt0 = -1e30f, mt1 = -1e30f;
#pragma unroll
        for (int n = 0; n < 4; n++) {
            mt0 = fmaxf(mt0, fmaxf(-s[n][0], -s[n][1]));
            mt1 = fmaxf(mt1, fmaxf(-s[n][2], -s[n][3]));
        }
        mt0 = fmaxf(mt0, __shfl_xor_sync(0xffffffffu, mt0, 1));
        mt0 = fmaxf(mt0, __shfl_xor_sync(0xffffffffu, mt0, 2));
        mt1 = fmaxf(mt1, __shfl_xor_sync(0xffffffffu, mt1, 1));
        mt1 = fmaxf(mt1, __shfl_xor_sync(0xffffffffu, mt1, 2));
        const float mn0 = fmaxf(m0, mt0), mn1 = fmaxf(m1, mt1);
        const float a0 = ex2((m0 - mn0)*L2E), a1 = ex2((m1 - mn1)*L2E);
        const float nm0 = -mn0*L2E, nm1 = -mn1*L2E;
        const bool resc = !__all_sync(0xffffffffu, (mn0 == m0) & (mn1 == m1));
        m0 = mn0; m1 = mn1;
        uint32_t ph[4][2];
        float sum0 = 0.f, sum1 = 0.f;
#pragma unroll
        for (int n = 0; n < 4; n++) {
            float p00 = ex2(fmaf(s[n][0], -L2E, nm0));
            float p01 = ex2(fmaf(s[n][1], -L2E, nm0));
            float p10 = ex2(fmaf(s[n][2], -L2E, nm1));
            float p11 = ex2(fmaf(s[n][3], -L2E, nm1));
            sum0 += p00 + p01; sum1 += p10 + p11;
            ph[n][0] = pack_h2(p00, p01);
            ph[n][1] = pack_h2(p10, p11);
        }
        l0 = l0*a0 + sum0; l1 = l1*a1 + sum1;
        if (resc) {
#pragma unroll
            for (int n = 0; n < 8; n++) {
                o[n][0] *= a0; o[n][1] *= a0; o[n][2] *= a1; o[n][3] *= a1;
            }
        }

        // ---- O += Ph.Vh over this warp's 32 j-rows
        {
            const int jadr = jhalf*32 + lane;
#pragma unroll
            for (int cn = 0; cn < 8; cn++) {
                uint32_t ad = kb + (uint32_t)(jadr*128) + (uint32_t)((cn*16) ^ ((jadr & 7)*16));
                uint32_t vh[4];
                ldsm4t(vh, ad);
#pragma unroll
                for (int t = 0; t < 2; t++) {
                    uint32_t aH[4] = { ph[2*t][0], ph[2*t][1], ph[2*t+1][0], ph[2*t+1][1] };
                    mma(o[cn], aH, vh[2*t], vh[2*t+1]);
                }
            }
        }
        GBAR(1 + jhalf);
    }

    // ---- combine the two j-halves within the CTA
    l0 += __shfl_xor_sync(0xffffffffu, l0, 1);
    l0 += __shfl_xor_sync(0xffffffffu, l0, 2);
    l1 += __shfl_xor_sync(0xffffffffu, l1, 1);
    l1 += __shfl_xor_sync(0xffffffffu, l1, 2);
    const int r0 = wg*16 + g, r1 = r0 + 8;
    if (lam == 0) {
        mex[jhalf][r0] = m0; lex[jhalf][r0] = l0;
        mex[jhalf][r1] = m1; lex[jhalf][r1] = l1;
    }
    __syncthreads();
    float mm0 = fmaxf(mex[0][r0], mex[1][r0]);
    float mm1 = fmaxf(mex[0][r1], mex[1][r1]);
    float Lt0 = lex[0][r0]*ex2((mex[0][r0]-mm0)*L2E) + lex[1][r0]*ex2((mex[1][r0]-mm0)*L2E);
    float Lt1 = lex[0][r1]*ex2((mex[0][r1]-mm1)*L2E) + lex[1][r1]*ex2((mex[1][r1]-mm1)*L2E);
    const float sc0 = ex2((m0 - mm0)*L2E) / Lt0;
    const float sc1 = ex2((m1 - mm1)*L2E) / Lt1;
    float* ob = reinterpret_cast<float*>(ks);
    __syncthreads();
    if (jhalf == 0) {
#pragma unroll
        for (int cn = 0; cn < 8; cn++) {
            const int c0 = 8*cn + 2*lam;
            ob[r0*65 + c0]     = o[cn][0]*sc0;
            ob[r0*65 + c0 + 1] = o[cn][1]*sc0;
            ob[r1*65 + c0]     = o[cn][2]*sc1;
            ob[r1*65 + c0 + 1] = o[cn][3]*sc1;
        }
    }
    __syncthreads();
    if (jhalf == 1) {
#pragma unroll
        for (int cn = 0; cn < 8; cn++) {
            const int c0 = 8*cn + 2*lam;
            ob[r0*65 + c0]     += o[cn][0]*sc0;
            ob[r0*65 + c0 + 1] += o[cn][1]*sc0;
            ob[r1*65 + c0]     += o[cn][2]*sc1;
            ob[r1*65 + c0 + 1] += o[cn][3]*sc1;
        }
    }
    __syncthreads();
    const float gam = gp[0];
#pragma unroll
    for (int k = 0; k < 16; k++) {
        int idx = tid + k*256;
        int c = idx >> 6, r = idx & 63;
        size_t oo = (size_t)(b*CH + c)*NPIX + i0 + r;
        out[oo] = gam*ob[r*65 + c] + g_y[oo];
    }
}

extern "C" void kernel_launch(void* const* d_in, const int* in_sizes, int n_in,
                              void* d_out, int out_size) {
    const float* x     = (const float*)d_in[0];
    const float* cw    = (const float*)d_in[1];
    const float* cb    = (const float*)d_in[2];
    const float* bns   = (const float*)d_in[3];
    const float* bnb   = (const float*)d_in[4];
    const float* pa    = (const float*)d_in[5];
    const float* gamma = (const float*)d_in[6];
    float* out = (float*)d_out;

    static bool done = false;
    if (!done) {
        cudaFuncSetAttribute(k_attn, cudaFuncAttributePreferredSharedMemoryCarveout, 100);
        done = true;
    }

    k_init_stats<<<1, 128>>>();
    k_conv<<<dim3(32, BATCH), 256>>>(x, cw, cb);
    k_bnt<<<dim3(64, BATCH), 256>>>(bns, bnb, pa);
    k_attn<<<dim3(64, BATCH), 256>>>(gamma, out);
}